// round 2
// baseline (speedup 1.0000x reference)
#include <cuda_runtime.h>
#include <math.h>

// Problem dims
#define Bn 32
#define Pn 256
#define Nn 1024
#define En 512
#define Hn 16
#define Dn 32

// Scratch (no allocations allowed)
__device__ float g_q[Bn*Hn*Pn*Dn];      // [B,H,P,D] q_first + q_last
__device__ float g_attn[Bn*Pn*En];      // [B,P,H*D] attention out (concat layout)
__device__ float g_mh[Bn*Pn*En];        // [B,P,E] combined heads
__device__ float g_rowsum[Bn*Pn];       // pointer-softmax denominators

// ---------------------------------------------------------------------------
// Kernel A: q = q_first + reshape(enc @ Wq^T)
// GEMM: [8192,512] x [512,512]^T, 64x64x16 tiles, 4x4 microtile
// ---------------------------------------------------------------------------
__global__ __launch_bounds__(256) void qlast_kernel(
    const float* __restrict__ enc, const float* __restrict__ Wq,
    const float* __restrict__ qf)
{
    const int mtile = blockIdx.y * 64, otile = blockIdx.x * 64;
    __shared__ float As[16][64];
    __shared__ float Ws[16][64];
    const int tid = threadIdx.x, tx = tid & 15, ty = tid >> 4;
    const int lr = tid >> 2, lk = (tid & 3) * 4;
    float acc[4][4] = {};

    for (int k0 = 0; k0 < 512; k0 += 16) {
        float4 a = *(const float4*)&enc[(mtile + lr) * 512 + k0 + lk];
        As[lk+0][lr] = a.x; As[lk+1][lr] = a.y; As[lk+2][lr] = a.z; As[lk+3][lr] = a.w;
        float4 w = *(const float4*)&Wq[(otile + lr) * 512 + k0 + lk];
        Ws[lk+0][lr] = w.x; Ws[lk+1][lr] = w.y; Ws[lk+2][lr] = w.z; Ws[lk+3][lr] = w.w;
        __syncthreads();
        #pragma unroll
        for (int kk = 0; kk < 16; kk++) {
            float4 av = *(const float4*)&As[kk][ty * 4];
            float4 bv = *(const float4*)&Ws[kk][tx * 4];
            float aa[4] = {av.x, av.y, av.z, av.w};
            float bb[4] = {bv.x, bv.y, bv.z, bv.w};
            #pragma unroll
            for (int i = 0; i < 4; i++)
                #pragma unroll
                for (int j = 0; j < 4; j++)
                    acc[i][j] += aa[i] * bb[j];
        }
        __syncthreads();
    }

    // Epilogue: scatter into [B,H,P,D] and add q_first
    const int o0 = otile + tx * 4;
    const int h = o0 >> 5, d0 = o0 & 31;   // 4 consecutive d stay within one head
    #pragma unroll
    for (int i = 0; i < 4; i++) {
        int m = mtile + ty * 4 + i;
        int b = m >> 8, p = m & 255;
        int idx = ((b * 16 + h) * 256 + p) * 32 + d0;
        float4 q4 = *(const float4*)&qf[idx];
        float4 o;
        o.x = acc[i][0] + q4.x; o.y = acc[i][1] + q4.y;
        o.z = acc[i][2] + q4.z; o.w = acc[i][3] + q4.w;
        *(float4*)&g_q[idx] = o;
    }
}

// ---------------------------------------------------------------------------
// Kernel B: fused masked MHA (flash-style, online softmax)
// grid: (B*H, P/64), block 256. Each thread: 1 row x 16-col group; acc[32].
// ---------------------------------------------------------------------------
__global__ __launch_bounds__(256, 2) void attn_kernel(
    const float* __restrict__ kmat, const float* __restrict__ vmat,
    const float* __restrict__ mask)
{
    const int bh = blockIdx.x;
    const int b = bh >> 4;
    const int p0 = blockIdx.y * 64;
    const int tid = threadIdx.x;
    const int row = tid >> 2, cg = tid & 3;
    const int p = p0 + row;

    __shared__ float ks[64 * 32];       // k chunk, [col][d] flat
    __shared__ float vt[32][65];        // v chunk transposed [d][col], padded

    // q row in registers (4 threads/row redundantly hold it; broadcast loads)
    float q[32];
    const float* qrow = &g_q[(bh * 256 + p) * 32];
    #pragma unroll
    for (int i = 0; i < 32; i += 4) {
        float4 t = *(const float4*)&qrow[i];
        q[i] = t.x; q[i+1] = t.y; q[i+2] = t.z; q[i+3] = t.w;
    }

    float acc[32];
    #pragma unroll
    for (int d = 0; d < 32; d++) acc[d] = 0.f;
    float mrun = -INFINITY, lrun = 0.f;

    const float* kbase = kmat + (size_t)bh * 1024 * 32;
    const float* vbase = vmat + (size_t)bh * 1024 * 32;
    const float* mrow  = mask + ((size_t)b * 256 + p) * 1024;
    const float inv_sqrt_d = 0.1767766952966369f;  // 1/sqrt(32)

    const int lcol = tid >> 2, lds = (tid & 3) * 8;

    for (int n0 = 0; n0 < 1024; n0 += 64) {
        // cooperative load: k flat, v transposed
        {
            const float4* ksrc = (const float4*)&kbase[(n0 + lcol) * 32 + lds];
            float4 k1 = ksrc[0], k2 = ksrc[1];
            *(float4*)&ks[lcol * 32 + lds]     = k1;
            *(float4*)&ks[lcol * 32 + lds + 4] = k2;
            const float4* vsrc = (const float4*)&vbase[(n0 + lcol) * 32 + lds];
            float4 v1 = vsrc[0], v2 = vsrc[1];
            vt[lds+0][lcol] = v1.x; vt[lds+1][lcol] = v1.y;
            vt[lds+2][lcol] = v1.z; vt[lds+3][lcol] = v1.w;
            vt[lds+4][lcol] = v2.x; vt[lds+5][lcol] = v2.y;
            vt[lds+6][lcol] = v2.z; vt[lds+7][lcol] = v2.w;
        }
        __syncthreads();

        // scores for this thread's 16 columns
        float s[16];
        #pragma unroll
        for (int j = 0; j < 16; j++) {
            const float* kc = &ks[(cg * 16 + j) * 32];
            float sa = 0.f;
            #pragma unroll
            for (int d = 0; d < 32; d += 4) {
                float4 k4 = *(const float4*)&kc[d];
                sa += q[d] * k4.x + q[d+1] * k4.y + q[d+2] * k4.z + q[d+3] * k4.w;
            }
            s[j] = sa * inv_sqrt_d;
        }
        // mask add
        #pragma unroll
        for (int j4 = 0; j4 < 16; j4 += 4) {
            float4 mk = *(const float4*)&mrow[n0 + cg * 16 + j4];
            s[j4]   += mk.x; s[j4+1] += mk.y; s[j4+2] += mk.z; s[j4+3] += mk.w;
        }
        // chunk max across this thread + 4-thread row group
        float mx = s[0];
        #pragma unroll
        for (int j = 1; j < 16; j++) mx = fmaxf(mx, s[j]);
        mx = fmaxf(mx, __shfl_xor_sync(0xffffffffu, mx, 1));
        mx = fmaxf(mx, __shfl_xor_sync(0xffffffffu, mx, 2));
        float mnew = fmaxf(mrun, mx);
        float corr = __expf(mrun - mnew);
        mrun = mnew;
        lrun *= corr;
        #pragma unroll
        for (int d = 0; d < 32; d++) acc[d] *= corr;
        #pragma unroll
        for (int j = 0; j < 16; j++) {
            s[j] = __expf(s[j] - mnew);
            lrun += s[j];
        }
        // PV accumulate: acc[d] += sum_j p_j * v[col_j][d]
        #pragma unroll
        for (int d = 0; d < 32; d++) {
            const float* vr = &vt[d][cg * 16];
            float a = acc[d];
            #pragma unroll
            for (int j = 0; j < 16; j++) a += s[j] * vr[j];
            acc[d] = a;
        }
        __syncthreads();
    }

    // reduce across the 4-thread row group
    #pragma unroll
    for (int d = 0; d < 32; d++) {
        acc[d] += __shfl_xor_sync(0xffffffffu, acc[d], 1);
        acc[d] += __shfl_xor_sync(0xffffffffu, acc[d], 2);
    }
    lrun += __shfl_xor_sync(0xffffffffu, lrun, 1);
    lrun += __shfl_xor_sync(0xffffffffu, lrun, 2);
    float inv = 1.f / lrun;

    // write out_concat [B,P,H*D]: thread cg writes d in [cg*8, cg*8+8)
    const int h = bh & 15;
    float* outp = &g_attn[((size_t)b * 256 + p) * 512 + h * 32];
    #pragma unroll
    for (int d = cg * 8; d < cg * 8 + 8; d += 4) {
        float4 o;
        o.x = acc[d] * inv; o.y = acc[d+1] * inv;
        o.z = acc[d+2] * inv; o.w = acc[d+3] * inv;
        *(float4*)&outp[d] = o;
    }
}

// ---------------------------------------------------------------------------
// Kernel C: mh = out_concat @ W_combine^T  (same shape as kernel A)
// ---------------------------------------------------------------------------
__global__ __launch_bounds__(256) void combine_kernel(const float* __restrict__ Wc)
{
    const int mtile = blockIdx.y * 64, otile = blockIdx.x * 64;
    __shared__ float As[16][64];
    __shared__ float Ws[16][64];
    const int tid = threadIdx.x, tx = tid & 15, ty = tid >> 4;
    const int lr = tid >> 2, lk = (tid & 3) * 4;
    float acc[4][4] = {};

    for (int k0 = 0; k0 < 512; k0 += 16) {
        float4 a = *(const float4*)&g_attn[(mtile + lr) * 512 + k0 + lk];
        As[lk+0][lr] = a.x; As[lk+1][lr] = a.y; As[lk+2][lr] = a.z; As[lk+3][lr] = a.w;
        float4 w = *(const float4*)&Wc[(otile + lr) * 512 + k0 + lk];
        Ws[lk+0][lr] = w.x; Ws[lk+1][lr] = w.y; Ws[lk+2][lr] = w.z; Ws[lk+3][lr] = w.w;
        __syncthreads();
        #pragma unroll
        for (int kk = 0; kk < 16; kk++) {
            float4 av = *(const float4*)&As[kk][ty * 4];
            float4 bv = *(const float4*)&Ws[kk][tx * 4];
            float aa[4] = {av.x, av.y, av.z, av.w};
            float bb[4] = {bv.x, bv.y, bv.z, bv.w};
            #pragma unroll
            for (int i = 0; i < 4; i++)
                #pragma unroll
                for (int j = 0; j < 4; j++)
                    acc[i][j] += aa[i] * bb[j];
        }
        __syncthreads();
    }
    #pragma unroll
    for (int i = 0; i < 4; i++) {
        int m = mtile + ty * 4 + i;
        float4 o;
        o.x = acc[i][0]; o.y = acc[i][1]; o.z = acc[i][2]; o.w = acc[i][3];
        *(float4*)&g_mh[m * 512 + otile + tx * 4] = o;
    }
}

// ---------------------------------------------------------------------------
// Kernel D: pointer scores + clipped-tanh softmax numerator
// score2 = mh @ shk / sqrt(E); out = exp(10*tanh(score2) + mask); rowsum atomics
// (tanh bounds logits to [-10,10] -> no max subtraction needed)
// ---------------------------------------------------------------------------
__global__ __launch_bounds__(256) void pointer_kernel(
    const float* __restrict__ shk, const float* __restrict__ mask,
    float* __restrict__ out)
{
    const int b = blockIdx.z;
    const int p0 = blockIdx.y * 64;
    const int n0 = blockIdx.x * 64;
    __shared__ float As[16][64];
    __shared__ float Bs[16][64];
    __shared__ float red[64][17];
    const int tid = threadIdx.x, tx = tid & 15, ty = tid >> 4;
    const int lr = tid >> 2, lk = (tid & 3) * 4;   // A loader
    const int br = tid >> 4, bc = (tid & 15) * 4;  // B loader
    float acc[4][4] = {};

    const float* Ab = g_mh + ((size_t)b * 256 + p0) * 512;
    const float* Bb = shk + (size_t)b * 512 * 1024 + n0;

    for (int k0 = 0; k0 < 512; k0 += 16) {
        float4 a = *(const float4*)&Ab[lr * 512 + k0 + lk];
        As[lk+0][lr] = a.x; As[lk+1][lr] = a.y; As[lk+2][lr] = a.z; As[lk+3][lr] = a.w;
        float4 bvv = *(const float4*)&Bb[(size_t)(k0 + br) * 1024 + bc];
        *(float4*)&Bs[br][bc] = bvv;
        __syncthreads();
        #pragma unroll
        for (int kk = 0; kk < 16; kk++) {
            float4 av = *(const float4*)&As[kk][ty * 4];
            float4 bv = *(const float4*)&Bs[kk][tx * 4];
            float aa[4] = {av.x, av.y, av.z, av.w};
            float bb[4] = {bv.x, bv.y, bv.z, bv.w};
            #pragma unroll
            for (int i = 0; i < 4; i++)
                #pragma unroll
                for (int j = 0; j < 4; j++)
                    acc[i][j] += aa[i] * bb[j];
        }
        __syncthreads();
    }

    const float invE = 0.04419417382415922f;  // 1/sqrt(512)
    #pragma unroll
    for (int i = 0; i < 4; i++) {
        int p = p0 + ty * 4 + i;
        int n = n0 + tx * 4;
        size_t oidx = ((size_t)b * 256 + p) * 1024 + n;
        float4 mk = *(const float4*)&mask[oidx];
        float mkv[4] = {mk.x, mk.y, mk.z, mk.w};
        float rs = 0.f;
        float vals[4];
        #pragma unroll
        for (int j = 0; j < 4; j++) {
            float t = 10.f * tanhf(acc[i][j] * invE);
            float e = __expf(t + mkv[j]);   // masked: exp(-1e9) == 0
            vals[j] = e; rs += e;
        }
        float4 o; o.x = vals[0]; o.y = vals[1]; o.z = vals[2]; o.w = vals[3];
        *(float4*)&out[oidx] = o;
        red[ty * 4 + i][tx] = rs;
    }
    __syncthreads();
    if (tid < 64) {
        float s = 0.f;
        #pragma unroll
        for (int t = 0; t < 16; t++) s += red[tid][t];
        atomicAdd(&g_rowsum[b * 256 + p0 + tid], s);
    }
}

// ---------------------------------------------------------------------------
// helpers: zero rowsums, final normalize
// ---------------------------------------------------------------------------
__global__ void zero_rowsum_kernel()
{
    int i = blockIdx.x * blockDim.x + threadIdx.x;
    if (i < Bn * Pn) g_rowsum[i] = 0.f;
}

__global__ void normalize_kernel(float* __restrict__ out)
{
    int i = blockIdx.x * blockDim.x + threadIdx.x;  // float4 index
    size_t i4 = (size_t)i * 4;
    int row = (int)(i4 >> 10);  // N=1024 per row, 4 | 1024
    float inv = 1.f / g_rowsum[row];
    float4 v = *(float4*)&out[i4];
    v.x *= inv; v.y *= inv; v.z *= inv; v.w *= inv;
    *(float4*)&out[i4] = v;
}

// ---------------------------------------------------------------------------
extern "C" void kernel_launch(void* const* d_in, const int* in_sizes, int n_in,
                              void* d_out, int out_size)
{
    const float* enc  = (const float*)d_in[0];  // encoded_last_node [B,P,E]
    const float* mask = (const float*)d_in[1];  // ninf_mask [B,P,N]
    const float* qf   = (const float*)d_in[2];  // q_first [B,H,P,D]
    const float* kmat = (const float*)d_in[3];  // k [B,H,N,D]
    const float* vmat = (const float*)d_in[4];  // v [B,H,N,D]
    const float* shk  = (const float*)d_in[5];  // single_head_key [B,E,N]
    const float* Wq   = (const float*)d_in[6];  // Wq_last [E,H*D]
    const float* Wc   = (const float*)d_in[7];  // W_combine [H*D,E]
    float* out = (float*)d_out;                 // probs [B,P,N]

    zero_rowsum_kernel<<<32, 256>>>();
    qlast_kernel<<<dim3(8, 128), 256>>>(enc, Wq, qf);
    attn_kernel<<<dim3(512, 4), 256>>>(kmat, vmat, mask);
    combine_kernel<<<dim3(8, 128), 256>>>(Wc);
    pointer_kernel<<<dim3(16, 4, 32), 256>>>(shk, mask, out);
    normalize_kernel<<<8192, 256>>>(out);
}

// round 3
// speedup vs baseline: 5.3347x; 5.3347x over previous
#include <cuda_runtime.h>
#include <cuda_bf16.h>
#include <math.h>

#define Bn 32
#define Pn 256
#define Nn 1024
#define En 512
#define Hn 16
#define Dn 32

__device__ float g_q[Bn*Hn*Pn*Dn];
__device__ float g_attn[Bn*Pn*En];
__device__ float g_mh[Bn*Pn*En];
__device__ float g_rowsum[Bn*Pn];

// ---- bf16x3 helpers -------------------------------------------------------
__device__ __forceinline__ void split_pack(float x0, float x1, unsigned &b, unsigned &s) {
    __nv_bfloat16 b0 = __float2bfloat16(x0), b1 = __float2bfloat16(x1);
    __nv_bfloat16 s0 = __float2bfloat16(x0 - __bfloat162float(b0));
    __nv_bfloat16 s1 = __float2bfloat16(x1 - __bfloat162float(b1));
    b = ((unsigned)__bfloat16_as_ushort(b1) << 16) | (unsigned)__bfloat16_as_ushort(b0);
    s = ((unsigned)__bfloat16_as_ushort(s1) << 16) | (unsigned)__bfloat16_as_ushort(s0);
}

__device__ __forceinline__ void mma16816(float* c, const unsigned* a, unsigned b0, unsigned b1) {
    asm("mma.sync.aligned.m16n8k16.row.col.f32.bf16.bf16.f32 "
        "{%0,%1,%2,%3}, {%4,%5,%6,%7}, {%8,%9}, {%0,%1,%2,%3};"
        : "+f"(c[0]), "+f"(c[1]), "+f"(c[2]), "+f"(c[3])
        : "r"(a[0]), "r"(a[1]), "r"(a[2]), "r"(a[3]), "r"(b0), "r"(b1));
}
__device__ __forceinline__ void mma3(float* c, const unsigned* ab, const unsigned* as,
                                     const unsigned* bb, const unsigned* bs) {
    mma16816(c, as, bb[0], bb[1]);
    mma16816(c, ab, bs[0], bs[1]);
    mma16816(c, ab, bb[0], bb[1]);
}
// A fragment from k-pair-packed smem S[kp][m] (m-stride 136)
__device__ __forceinline__ void ldA(unsigned f[4], const unsigned (*S)[136], int kpt, int mg) {
    f[0] = S[kpt][mg]; f[1] = S[kpt][mg+8]; f[2] = S[kpt+4][mg]; f[3] = S[kpt+4][mg+8];
}
__device__ __forceinline__ void ldB(unsigned f[2], const unsigned (*S)[136], int kpt, int ng) {
    f[0] = S[kpt][ng]; f[1] = S[kpt+4][ng];
}

// ---------------------------------------------------------------------------
// Dense GEMM bf16x3: C = A[M,512] @ W[Nw,512]^T, 128x128 tile, kstep 32.
// EPI 0: scatter to g_q [B,H,P,D] + add q_first. EPI 1: row-major ld=512.
// ---------------------------------------------------------------------------
template<int EPI>
__global__ __launch_bounds__(256) void gemm_k(const float* __restrict__ A,
                                              const float* __restrict__ W,
                                              const float* __restrict__ qf,
                                              float* __restrict__ C)
{
    __shared__ unsigned Ab[16][136], As[16][136], Bb[16][136], Bs[16][136];
    const int tid = threadIdx.x, lane = tid & 31;
    const int g = lane >> 2, t = lane & 3, wid = tid >> 5;
    const int wm = wid >> 2, wn = wid & 3;
    const int mblk = blockIdx.y * 128, nblk = blockIdx.x * 128;
    const int lrow = tid >> 1, lcg = (tid & 1) * 16;

    const float* Ap = A + (size_t)(mblk + lrow) * 512 + lcg;
    const float* Wp = W + (size_t)(nblk + lrow) * 512 + lcg;

    float acc[4][4][4];
    #pragma unroll
    for (int i = 0; i < 4; i++) for (int j = 0; j < 4; j++) for (int r = 0; r < 4; r++)
        acc[i][j][r] = 0.f;

    float4 ar[4], wr[4];
    #pragma unroll
    for (int c = 0; c < 4; c++) { ar[c] = *(const float4*)(Ap + c*4); wr[c] = *(const float4*)(Wp + c*4); }

    for (int k0 = 0; k0 < 512; k0 += 32) {
        #pragma unroll
        for (int c = 0; c < 4; c++) {
            int kp = (lcg + c*4) >> 1; unsigned bb, ss;
            split_pack(ar[c].x, ar[c].y, bb, ss); Ab[kp][lrow] = bb; As[kp][lrow] = ss;
            split_pack(ar[c].z, ar[c].w, bb, ss); Ab[kp+1][lrow] = bb; As[kp+1][lrow] = ss;
            split_pack(wr[c].x, wr[c].y, bb, ss); Bb[kp][lrow] = bb; Bs[kp][lrow] = ss;
            split_pack(wr[c].z, wr[c].w, bb, ss); Bb[kp+1][lrow] = bb; Bs[kp+1][lrow] = ss;
        }
        __syncthreads();
        if (k0 + 32 < 512) {
            #pragma unroll
            for (int c = 0; c < 4; c++) {
                ar[c] = *(const float4*)(Ap + k0 + 32 + c*4);
                wr[c] = *(const float4*)(Wp + k0 + 32 + c*4);
            }
        }
        #pragma unroll
        for (int ks = 0; ks < 2; ks++) {
            const int kb = ks * 8;
            unsigned afb[4][4], afs[4][4], bfb[4][2], bfs[4][2];
            #pragma unroll
            for (int mt = 0; mt < 4; mt++) {
                ldA(afb[mt], Ab, kb + t, wm*64 + mt*16 + g);
                ldA(afs[mt], As, kb + t, wm*64 + mt*16 + g);
            }
            #pragma unroll
            for (int nt = 0; nt < 4; nt++) {
                ldB(bfb[nt], Bb, kb + t, wn*32 + nt*8 + g);
                ldB(bfs[nt], Bs, kb + t, wn*32 + nt*8 + g);
            }
            #pragma unroll
            for (int mt = 0; mt < 4; mt++)
                #pragma unroll
                for (int nt = 0; nt < 4; nt++)
                    mma3(acc[mt][nt], afb[mt], afs[mt], bfb[nt], bfs[nt]);
        }
        __syncthreads();
    }

    #pragma unroll
    for (int mt = 0; mt < 4; mt++)
        #pragma unroll
        for (int nt = 0; nt < 4; nt++)
            #pragma unroll
            for (int rr = 0; rr < 2; rr++) {
                int m = mblk + wm*64 + mt*16 + g + rr*8;
                int n = nblk + wn*32 + nt*8 + 2*t;
                float v0 = acc[mt][nt][rr*2], v1 = acc[mt][nt][rr*2+1];
                if (EPI == 0) {
                    int b = m >> 8, p = m & 255, h = n >> 5, d = n & 31;
                    size_t idx = (((size_t)b*16 + h)*256 + p)*32 + d;
                    float2 q2 = *(const float2*)(qf + idx);
                    float2 o; o.x = v0 + q2.x; o.y = v1 + q2.y;
                    *(float2*)(C + idx) = o;
                } else {
                    float2 o; o.x = v0; o.y = v1;
                    *(float2*)(C + (size_t)m*512 + n) = o;
                }
            }
}

// ---------------------------------------------------------------------------
// Fused attention: QK^T -> exp (no max; scores bounded) -> PV, all bf16x3 mma.
// grid (B*H, P/128), 256 thr, 125440 B dynamic smem.
// ---------------------------------------------------------------------------
__global__ __launch_bounds__(256, 1) void attn_k(const float* __restrict__ kmat,
                                                 const float* __restrict__ vmat,
                                                 const float* __restrict__ mask)
{
    extern __shared__ unsigned sm[];
    unsigned (*Qb)[136] = (unsigned(*)[136])(sm);
    unsigned (*Qs)[136] = (unsigned(*)[136])(sm + 2176);
    unsigned (*Kb)[136] = (unsigned(*)[136])(sm + 4352);
    unsigned (*Ks)[136] = (unsigned(*)[136])(sm + 6528);
    unsigned (*Vb)[40]  = (unsigned(*)[40]) (sm + 8704);
    unsigned (*Vs)[40]  = (unsigned(*)[40]) (sm + 11264);
    unsigned (*Pb)[136] = (unsigned(*)[136])(sm + 13824);
    unsigned (*Ps)[136] = (unsigned(*)[136])(sm + 22528);
    float* rsum = (float*)(sm + 31232);

    const int bh = blockIdx.x, b = bh >> 4, h = bh & 15;
    const int p0 = blockIdx.y * 128;
    const int tid = threadIdx.x, lane = tid & 31;
    const int g = lane >> 2, t = lane & 3, wid = tid >> 5;
    const int wm = wid >> 2, wn = wid & 3;
    const int lrow = tid >> 1, lcg = (tid & 1) * 16;
    const float scale = 0.1767766952966369f;  // 1/sqrt(32)

    // Q tile -> smem (split, k-pair packed)
    {
        const float* qp = g_q + ((size_t)bh*256 + p0 + lrow)*32 + lcg;
        #pragma unroll
        for (int c = 0; c < 4; c++) {
            float4 v = *(const float4*)(qp + c*4);
            int kp = (lcg + c*4) >> 1; unsigned bb, ss;
            split_pack(v.x, v.y, bb, ss); Qb[kp][lrow] = bb; Qs[kp][lrow] = ss;
            split_pack(v.z, v.w, bb, ss); Qb[kp+1][lrow] = bb; Qs[kp+1][lrow] = ss;
        }
    }
    if (tid < 128) rsum[tid] = 0.f;

    float oacc[4][4];
    #pragma unroll
    for (int i = 0; i < 4; i++) for (int j = 0; j < 4; j++) oacc[i][j] = 0.f;
    float rs[4][2];
    #pragma unroll
    for (int i = 0; i < 4; i++) { rs[i][0] = 0.f; rs[i][1] = 0.f; }

    const float* kb0 = kmat + (size_t)bh * (1024*32);
    const float* vb0 = vmat + (size_t)bh * (1024*32);
    float4 kr[4], vr[4];
    #pragma unroll
    for (int c = 0; c < 4; c++) {
        kr[c] = *(const float4*)(kb0 + (size_t)lrow*32 + lcg + c*4);
        vr[c] = *(const float4*)(vb0 + (size_t)lrow*32 + lcg + c*4);
    }

    for (int n0 = 0; n0 < 1024; n0 += 128) {
        // stage K (k-pair packed) and V (n-pair packed halves)
        {
            __nv_bfloat16* Vbh = (__nv_bfloat16*)Vb;
            __nv_bfloat16* Vsh = (__nv_bfloat16*)Vs;
            const int np = lrow >> 1, half = lrow & 1;
            #pragma unroll
            for (int c = 0; c < 4; c++) {
                int kp = (lcg + c*4) >> 1; unsigned bb, ss;
                split_pack(kr[c].x, kr[c].y, bb, ss); Kb[kp][lrow] = bb; Ks[kp][lrow] = ss;
                split_pack(kr[c].z, kr[c].w, bb, ss); Kb[kp+1][lrow] = bb; Ks[kp+1][lrow] = ss;
                float vv[4] = {vr[c].x, vr[c].y, vr[c].z, vr[c].w};
                #pragma unroll
                for (int i = 0; i < 4; i++) {
                    int d = lcg + c*4 + i;
                    __nv_bfloat16 hb = __float2bfloat16(vv[i]);
                    __nv_bfloat16 hs = __float2bfloat16(vv[i] - __bfloat162float(hb));
                    Vbh[(np*40 + d)*2 + half] = hb;
                    Vsh[(np*40 + d)*2 + half] = hs;
                }
            }
        }
        __syncthreads();
        if (n0 + 128 < 1024) {
            #pragma unroll
            for (int c = 0; c < 4; c++) {
                kr[c] = *(const float4*)(kb0 + (size_t)(n0 + 128 + lrow)*32 + lcg + c*4);
                vr[c] = *(const float4*)(vb0 + (size_t)(n0 + 128 + lrow)*32 + lcg + c*4);
            }
        }

        // QK^T: warp tile 64x32, k = 32
        float sacc[4][4][4];
        #pragma unroll
        for (int i = 0; i < 4; i++) for (int j = 0; j < 4; j++) for (int r = 0; r < 4; r++)
            sacc[i][j][r] = 0.f;
        #pragma unroll
        for (int ks = 0; ks < 2; ks++) {
            const int kb = ks * 8;
            unsigned afb[4][4], afs[4][4], bfb[4][2], bfs[4][2];
            #pragma unroll
            for (int mt = 0; mt < 4; mt++) {
                ldA(afb[mt], Qb, kb + t, wm*64 + mt*16 + g);
                ldA(afs[mt], Qs, kb + t, wm*64 + mt*16 + g);
            }
            #pragma unroll
            for (int nt = 0; nt < 4; nt++) {
                ldB(bfb[nt], Kb, kb + t, wn*32 + nt*8 + g);
                ldB(bfs[nt], Ks, kb + t, wn*32 + nt*8 + g);
            }
            #pragma unroll
            for (int mt = 0; mt < 4; mt++)
                #pragma unroll
                for (int nt = 0; nt < 4; nt++)
                    mma3(sacc[mt][nt], afb[mt], afs[mt], bfb[nt], bfs[nt]);
        }

        // exp + mask; pack P (n-pair packed) into smem; accumulate rowsums
        #pragma unroll
        for (int mt = 0; mt < 4; mt++) {
            const int ml = wm*64 + mt*16 + g;
            const size_t mr0 = ((size_t)b*256 + p0 + ml)*1024 + n0;
            #pragma unroll
            for (int nt = 0; nt < 4; nt++) {
                const int nl = wn*32 + nt*8 + 2*t;
                float2 mk0 = *(const float2*)(mask + mr0 + nl);
                float2 mk1 = *(const float2*)(mask + mr0 + 8*1024 + nl);
                float e0 = __expf(fmaf(sacc[mt][nt][0], scale, mk0.x));
                float e1 = __expf(fmaf(sacc[mt][nt][1], scale, mk0.y));
                float e2 = __expf(fmaf(sacc[mt][nt][2], scale, mk1.x));
                float e3 = __expf(fmaf(sacc[mt][nt][3], scale, mk1.y));
                rs[mt][0] += e0 + e1; rs[mt][1] += e2 + e3;
                unsigned bb, ss;
                const int np = wn*16 + nt*4 + t;
                split_pack(e0, e1, bb, ss); Pb[np][ml]   = bb; Ps[np][ml]   = ss;
                split_pack(e2, e3, bb, ss); Pb[np][ml+8] = bb; Ps[np][ml+8] = ss;
            }
        }
        __syncthreads();

        // PV: warp handles rows wid*16..+15, d = 0..31, k = n (128)
        #pragma unroll
        for (int ks = 0; ks < 8; ks++) {
            unsigned afb[4], afs[4], bfb[2], bfs[2];
            ldA(afb, Pb, ks*8 + t, wid*16 + g);
            ldA(afs, Ps, ks*8 + t, wid*16 + g);
            #pragma unroll
            for (int nt = 0; nt < 4; nt++) {
                const int dg = nt*8 + g;
                bfb[0] = Vb[ks*8 + t][dg]; bfb[1] = Vb[ks*8 + t + 4][dg];
                bfs[0] = Vs[ks*8 + t][dg]; bfs[1] = Vs[ks*8 + t + 4][dg];
                mma3(oacc[nt], afb, afs, bfb, bfs);
            }
        }
        __syncthreads();
    }

    // rowsums -> smem (reduce over t, then over the 4 wn warps via atomics)
    #pragma unroll
    for (int mt = 0; mt < 4; mt++) {
        #pragma unroll
        for (int rr = 0; rr < 2; rr++) {
            float v = rs[mt][rr];
            v += __shfl_xor_sync(0xffffffffu, v, 1);
            v += __shfl_xor_sync(0xffffffffu, v, 2);
            if (t == 0) atomicAdd(&rsum[wm*64 + mt*16 + g + rr*8], v);
        }
    }
    __syncthreads();

    // normalize + write out_concat [B,P,H*D]
    const float inv0 = 1.f / rsum[wid*16 + g];
    const float inv1 = 1.f / rsum[wid*16 + g + 8];
    float* op = g_attn + ((size_t)b*256 + p0 + wid*16 + g)*512 + h*32;
    #pragma unroll
    for (int nt = 0; nt < 4; nt++) {
        float2 o0; o0.x = oacc[nt][0]*inv0; o0.y = oacc[nt][1]*inv0;
        float2 o1; o1.x = oacc[nt][2]*inv1; o1.y = oacc[nt][3]*inv1;
        *(float2*)(op + nt*8 + 2*t) = o0;
        *(float2*)(op + 8*512 + nt*8 + 2*t) = o1;
    }
}

// ---------------------------------------------------------------------------
// Pointer GEMM bf16x3 + tanh-clip softmax numerator. grid (N/128, P/128, B).
// ---------------------------------------------------------------------------
__global__ __launch_bounds__(256) void pointer_k(const float* __restrict__ shk,
                                                 const float* __restrict__ mask,
                                                 float* __restrict__ out)
{
    __shared__ unsigned Ab[16][136], As[16][136], Bb[16][136], Bs[16][136];
    const int tid = threadIdx.x, lane = tid & 31;
    const int g = lane >> 2, t = lane & 3, wid = tid >> 5;
    const int wm = wid >> 2, wn = wid & 3;
    const int b = blockIdx.z, pblk = blockIdx.y * 128, nblk = blockIdx.x * 128;
    const int lrow = tid >> 1, lcg = (tid & 1) * 16;

    const float* Ap = g_mh + ((size_t)b*256 + pblk + lrow)*512 + lcg;
    const float* Bp = shk + (size_t)b*512*1024 + nblk + (tid & 31)*4;
    const int kplo = wid;  // 0..7

    float acc[4][4][4];
    #pragma unroll
    for (int i = 0; i < 4; i++) for (int j = 0; j < 4; j++) for (int r = 0; r < 4; r++)
        acc[i][j][r] = 0.f;

    float4 ar[4], br[2][2];
    #pragma unroll
    for (int c = 0; c < 4; c++) ar[c] = *(const float4*)(Ap + c*4);
    #pragma unroll
    for (int j = 0; j < 2; j++) {
        br[j][0] = *(const float4*)(Bp + (size_t)(2*(kplo + j*8))*1024);
        br[j][1] = *(const float4*)(Bp + (size_t)(2*(kplo + j*8) + 1)*1024);
    }

    for (int k0 = 0; k0 < 512; k0 += 32) {
        #pragma unroll
        for (int c = 0; c < 4; c++) {
            int kp = (lcg + c*4) >> 1; unsigned bb, ss;
            split_pack(ar[c].x, ar[c].y, bb, ss); Ab[kp][lrow] = bb; As[kp][lrow] = ss;
            split_pack(ar[c].z, ar[c].w, bb, ss); Ab[kp+1][lrow] = bb; As[kp+1][lrow] = ss;
        }
        #pragma unroll
        for (int j = 0; j < 2; j++) {
            const int kp = kplo + j*8, n4 = (tid & 31)*4;
            unsigned pb[4], ps[4];
            split_pack(br[j][0].x, br[j][1].x, pb[0], ps[0]);
            split_pack(br[j][0].y, br[j][1].y, pb[1], ps[1]);
            split_pack(br[j][0].z, br[j][1].z, pb[2], ps[2]);
            split_pack(br[j][0].w, br[j][1].w, pb[3], ps[3]);
            *(uint4*)&Bb[kp][n4] = *(uint4*)pb;
            *(uint4*)&Bs[kp][n4] = *(uint4*)ps;
        }
        __syncthreads();
        if (k0 + 32 < 512) {
            #pragma unroll
            for (int c = 0; c < 4; c++) ar[c] = *(const float4*)(Ap + k0 + 32 + c*4);
            #pragma unroll
            for (int j = 0; j < 2; j++) {
                br[j][0] = *(const float4*)(Bp + (size_t)(k0 + 32 + 2*(kplo + j*8))*1024);
                br[j][1] = *(const float4*)(Bp + (size_t)(k0 + 32 + 2*(kplo + j*8) + 1)*1024);
            }
        }
        #pragma unroll
        for (int ks = 0; ks < 2; ks++) {
            const int kb = ks * 8;
            unsigned afb[4][4], afs[4][4], bfb[4][2], bfs[4][2];
            #pragma unroll
            for (int mt = 0; mt < 4; mt++) {
                ldA(afb[mt], Ab, kb + t, wm*64 + mt*16 + g);
                ldA(afs[mt], As, kb + t, wm*64 + mt*16 + g);
            }
            #pragma unroll
            for (int nt = 0; nt < 4; nt++) {
                ldB(bfb[nt], Bb, kb + t, wn*32 + nt*8 + g);
                ldB(bfs[nt], Bs, kb + t, wn*32 + nt*8 + g);
            }
            #pragma unroll
            for (int mt = 0; mt < 4; mt++)
                #pragma unroll
                for (int nt = 0; nt < 4; nt++)
                    mma3(acc[mt][nt], afb[mt], afs[mt], bfb[nt], bfs[nt]);
        }
        __syncthreads();
    }

    const float invE = 0.04419417382415922f;  // 1/sqrt(512)
    #pragma unroll
    for (int mt = 0; mt < 4; mt++) {
        float rsl[2] = {0.f, 0.f};
        #pragma unroll
        for (int rr = 0; rr < 2; rr++) {
            const int p = pblk + wm*64 + mt*16 + g + rr*8;
            #pragma unroll
            for (int nt = 0; nt < 4; nt++) {
                const int n = nblk + wn*32 + nt*8 + 2*t;
                size_t oi = ((size_t)b*256 + p)*1024 + n;
                float2 mk = *(const float2*)(mask + oi);
                float e0 = __expf(10.f*tanhf(acc[mt][nt][rr*2]  *invE) + mk.x);
                float e1 = __expf(10.f*tanhf(acc[mt][nt][rr*2+1]*invE) + mk.y);
                rsl[rr] += e0 + e1;
                float2 o; o.x = e0; o.y = e1;
                *(float2*)(out + oi) = o;
            }
        }
        #pragma unroll
        for (int rr = 0; rr < 2; rr++) {
            float v = rsl[rr];
            v += __shfl_xor_sync(0xffffffffu, v, 1);
            v += __shfl_xor_sync(0xffffffffu, v, 2);
            if (t == 0)
                atomicAdd(&g_rowsum[b*256 + pblk + wm*64 + mt*16 + g + rr*8], v);
        }
    }
}

// ---------------------------------------------------------------------------
__global__ void zero_rowsum_k()
{
    int i = blockIdx.x * blockDim.x + threadIdx.x;
    if (i < Bn*Pn) g_rowsum[i] = 0.f;
}

__global__ void normalize_k(float* __restrict__ out)
{
    int i = blockIdx.x * blockDim.x + threadIdx.x;
    size_t i4 = (size_t)i * 4;
    int row = (int)(i4 >> 10);
    float inv = 1.f / g_rowsum[row];
    float4 v = *(float4*)&out[i4];
    v.x *= inv; v.y *= inv; v.z *= inv; v.w *= inv;
    *(float4*)&out[i4] = v;
}

// ---------------------------------------------------------------------------
extern "C" void kernel_launch(void* const* d_in, const int* in_sizes, int n_in,
                              void* d_out, int out_size)
{
    const float* enc  = (const float*)d_in[0];
    const float* mask = (const float*)d_in[1];
    const float* qf   = (const float*)d_in[2];
    const float* kmat = (const float*)d_in[3];
    const float* vmat = (const float*)d_in[4];
    const float* shk  = (const float*)d_in[5];
    const float* Wq   = (const float*)d_in[6];
    const float* Wc   = (const float*)d_in[7];
    float* out = (float*)d_out;

    float* gq; cudaGetSymbolAddress((void**)&gq, g_q);
    float* ga; cudaGetSymbolAddress((void**)&ga, g_attn);
    float* gm; cudaGetSymbolAddress((void**)&gm, g_mh);

    cudaFuncSetAttribute(attn_k, cudaFuncAttributeMaxDynamicSharedMemorySize, 125440);

    zero_rowsum_k<<<32, 256>>>();
    gemm_k<0><<<dim3(4, 64), 256>>>(enc, Wq, qf, gq);
    attn_k<<<dim3(512, 2), 256, 125440>>>(kmat, vmat, mask);
    gemm_k<1><<<dim3(4, 64), 256>>>(ga, Wc, qf, gm);
    pointer_k<<<dim3(8, 2, 32), 256>>>(shk, mask, out);
    normalize_k<<<8192, 256>>>(out);
}

// round 4
// speedup vs baseline: 5.8507x; 1.0967x over previous
#include <cuda_runtime.h>
#include <cuda_bf16.h>
#include <math.h>

#define Bn 32
#define Pn 256
#define Nn 1024
#define En 512
#define Hn 16
#define Dn 32

__device__ float g_q[Bn*Hn*Pn*Dn];
__device__ float g_attn[Bn*Pn*En];
__device__ float g_mh[Bn*Pn*En];
__device__ float g_rowsum[Bn*Pn];

// ---- bf16x3 helpers -------------------------------------------------------
__device__ __forceinline__ void split_pack(float x0, float x1, unsigned &b, unsigned &s) {
    __nv_bfloat16 b0 = __float2bfloat16(x0), b1 = __float2bfloat16(x1);
    __nv_bfloat16 s0 = __float2bfloat16(x0 - __bfloat162float(b0));
    __nv_bfloat16 s1 = __float2bfloat16(x1 - __bfloat162float(b1));
    b = ((unsigned)__bfloat16_as_ushort(b1) << 16) | (unsigned)__bfloat16_as_ushort(b0);
    s = ((unsigned)__bfloat16_as_ushort(s1) << 16) | (unsigned)__bfloat16_as_ushort(s0);
}

__device__ __forceinline__ void mma16816(float* c, const unsigned* a, unsigned b0, unsigned b1) {
    asm("mma.sync.aligned.m16n8k16.row.col.f32.bf16.bf16.f32 "
        "{%0,%1,%2,%3}, {%4,%5,%6,%7}, {%8,%9}, {%0,%1,%2,%3};"
        : "+f"(c[0]), "+f"(c[1]), "+f"(c[2]), "+f"(c[3])
        : "r"(a[0]), "r"(a[1]), "r"(a[2]), "r"(a[3]), "r"(b0), "r"(b1));
}
__device__ __forceinline__ void mma3(float* c, const unsigned* ab, const unsigned* as,
                                     const unsigned* bb, const unsigned* bs) {
    mma16816(c, as, bb[0], bb[1]);
    mma16816(c, ab, bs[0], bs[1]);
    mma16816(c, ab, bb[0], bb[1]);
}
template<int STR>
__device__ __forceinline__ void ldA(unsigned f[4], const unsigned (*S)[STR], int kpt, int mg) {
    f[0] = S[kpt][mg]; f[1] = S[kpt][mg+8]; f[2] = S[kpt+4][mg]; f[3] = S[kpt+4][mg+8];
}
template<int STR>
__device__ __forceinline__ void ldB(unsigned f[2], const unsigned (*S)[STR], int kpt, int ng) {
    f[0] = S[kpt][ng]; f[1] = S[kpt+4][ng];
}

// ---------------------------------------------------------------------------
// Dense GEMM bf16x3 (unchanged from R3)
// ---------------------------------------------------------------------------
template<int EPI>
__global__ __launch_bounds__(256) void gemm_k(const float* __restrict__ A,
                                              const float* __restrict__ W,
                                              const float* __restrict__ qf,
                                              float* __restrict__ C)
{
    __shared__ unsigned Ab[16][136], As[16][136], Bb[16][136], Bs[16][136];
    const int tid = threadIdx.x, lane = tid & 31;
    const int g = lane >> 2, t = lane & 3, wid = tid >> 5;
    const int wm = wid >> 2, wn = wid & 3;
    const int mblk = blockIdx.y * 128, nblk = blockIdx.x * 128;
    const int lrow = tid >> 1, lcg = (tid & 1) * 16;

    const float* Ap = A + (size_t)(mblk + lrow) * 512 + lcg;
    const float* Wp = W + (size_t)(nblk + lrow) * 512 + lcg;

    float acc[4][4][4];
    #pragma unroll
    for (int i = 0; i < 4; i++) for (int j = 0; j < 4; j++) for (int r = 0; r < 4; r++)
        acc[i][j][r] = 0.f;

    float4 ar[4], wr[4];
    #pragma unroll
    for (int c = 0; c < 4; c++) { ar[c] = *(const float4*)(Ap + c*4); wr[c] = *(const float4*)(Wp + c*4); }

    for (int k0 = 0; k0 < 512; k0 += 32) {
        #pragma unroll
        for (int c = 0; c < 4; c++) {
            int kp = (lcg + c*4) >> 1; unsigned bb, ss;
            split_pack(ar[c].x, ar[c].y, bb, ss); Ab[kp][lrow] = bb; As[kp][lrow] = ss;
            split_pack(ar[c].z, ar[c].w, bb, ss); Ab[kp+1][lrow] = bb; As[kp+1][lrow] = ss;
            split_pack(wr[c].x, wr[c].y, bb, ss); Bb[kp][lrow] = bb; Bs[kp][lrow] = ss;
            split_pack(wr[c].z, wr[c].w, bb, ss); Bb[kp+1][lrow] = bb; Bs[kp+1][lrow] = ss;
        }
        __syncthreads();
        if (k0 + 32 < 512) {
            #pragma unroll
            for (int c = 0; c < 4; c++) {
                ar[c] = *(const float4*)(Ap + k0 + 32 + c*4);
                wr[c] = *(const float4*)(Wp + k0 + 32 + c*4);
            }
        }
        #pragma unroll
        for (int ks = 0; ks < 2; ks++) {
            const int kb = ks * 8;
            unsigned afb[4][4], afs[4][4], bfb[4][2], bfs[4][2];
            #pragma unroll
            for (int mt = 0; mt < 4; mt++) {
                ldA<136>(afb[mt], Ab, kb + t, wm*64 + mt*16 + g);
                ldA<136>(afs[mt], As, kb + t, wm*64 + mt*16 + g);
            }
            #pragma unroll
            for (int nt = 0; nt < 4; nt++) {
                ldB<136>(bfb[nt], Bb, kb + t, wn*32 + nt*8 + g);
                ldB<136>(bfs[nt], Bs, kb + t, wn*32 + nt*8 + g);
            }
            #pragma unroll
            for (int mt = 0; mt < 4; mt++)
                #pragma unroll
                for (int nt = 0; nt < 4; nt++)
                    mma3(acc[mt][nt], afb[mt], afs[mt], bfb[nt], bfs[nt]);
        }
        __syncthreads();
    }

    #pragma unroll
    for (int mt = 0; mt < 4; mt++)
        #pragma unroll
        for (int nt = 0; nt < 4; nt++)
            #pragma unroll
            for (int rr = 0; rr < 2; rr++) {
                int m = mblk + wm*64 + mt*16 + g + rr*8;
                int n = nblk + wn*32 + nt*8 + 2*t;
                float v0 = acc[mt][nt][rr*2], v1 = acc[mt][nt][rr*2+1];
                if (EPI == 0) {
                    int b = m >> 8, p = m & 255, h = n >> 5, d = n & 31;
                    size_t idx = (((size_t)b*16 + h)*256 + p)*32 + d;
                    float2 q2 = *(const float2*)(qf + idx);
                    float2 o; o.x = v0 + q2.x; o.y = v1 + q2.y;
                    *(float2*)(C + idx) = o;
                } else {
                    float2 o; o.x = v0; o.y = v1;
                    *(float2*)(C + (size_t)m*512 + n) = o;
                }
            }
}

// ---------------------------------------------------------------------------
// Fused attention v2: warp-row-strip, P stays in registers (C->A frag reuse),
// no rowsum atomics, 36.9KB static smem, 2 CTAs/SM.
// grid (B*H, P/128), 256 threads.
// ---------------------------------------------------------------------------
__global__ __launch_bounds__(256, 2) void attn_k(const float* __restrict__ kmat,
                                                 const float* __restrict__ vmat,
                                                 const float* __restrict__ mask)
{
    __shared__ unsigned Qb[16][136], Qs[16][136];
    __shared__ unsigned Kb[16][72],  Ks[16][72];
    __shared__ unsigned Vb[32][40],  Vs[32][40];

    const int bh = blockIdx.x, b = bh >> 4, h = bh & 15;
    const int p0 = blockIdx.y * 128;
    const int tid = threadIdx.x, lane = tid & 31;
    const int g = lane >> 2, t = lane & 3, w = tid >> 5;
    const int m0 = w * 16;
    const float scale = 0.1767766952966369f;  // 1/sqrt(32)

    // stage Q (full 128 rows, split + k-pair packed) — covered by first in-loop sync
    {
        const int lrow = tid >> 1, lcg = (tid & 1) * 16;
        const float* qp = g_q + ((size_t)bh*256 + p0 + lrow)*32 + lcg;
        #pragma unroll
        for (int c = 0; c < 4; c++) {
            float4 v = *(const float4*)(qp + c*4);
            int kp = (lcg + c*4) >> 1; unsigned bb, ss;
            split_pack(v.x, v.y, bb, ss); Qb[kp][lrow] = bb; Qs[kp][lrow] = ss;
            split_pack(v.z, v.w, bb, ss); Qb[kp+1][lrow] = bb; Qs[kp+1][lrow] = ss;
        }
    }

    // staging role: threads 0-127 stage K, 128-255 stage V (64 rows x 32 d each)
    const int srow = tid & 63;
    const int sd = ((tid >> 6) & 1) * 16;
    const bool doV = tid >= 128;
    const float* kb0 = kmat + (size_t)bh * (1024*32);
    const float* vb0 = vmat + (size_t)bh * (1024*32);
    const float* mbase = mask + ((size_t)b*256 + p0 + m0 + g)*1024;

    float oacc[4][4];
    #pragma unroll
    for (int i = 0; i < 4; i++) for (int j = 0; j < 4; j++) oacc[i][j] = 0.f;
    float rs0 = 0.f, rs1 = 0.f;

    for (int n0 = 0; n0 < 1024; n0 += 64) {
        if (!doV) {
            const float* kp_ = kb0 + (size_t)(n0 + srow)*32 + sd;
            #pragma unroll
            for (int c = 0; c < 4; c++) {
                float4 v = *(const float4*)(kp_ + c*4);
                int kp = (sd + c*4) >> 1; unsigned bb, ss;
                split_pack(v.x, v.y, bb, ss); Kb[kp][srow] = bb; Ks[kp][srow] = ss;
                split_pack(v.z, v.w, bb, ss); Kb[kp+1][srow] = bb; Ks[kp+1][srow] = ss;
            }
        } else {
            const float* vp_ = vb0 + (size_t)(n0 + srow)*32 + sd;
            __nv_bfloat16* Vbh = (__nv_bfloat16*)Vb;
            __nv_bfloat16* Vsh = (__nv_bfloat16*)Vs;
            const int np = srow >> 1, half = srow & 1;
            #pragma unroll
            for (int c = 0; c < 4; c++) {
                float4 v = *(const float4*)(vp_ + c*4);
                float vv[4] = {v.x, v.y, v.z, v.w};
                #pragma unroll
                for (int i = 0; i < 4; i++) {
                    int d = sd + c*4 + i;
                    __nv_bfloat16 hb = __float2bfloat16(vv[i]);
                    __nv_bfloat16 hs = __float2bfloat16(vv[i] - __bfloat162float(hb));
                    Vbh[(np*40 + d)*2 + half] = hb;
                    Vsh[(np*40 + d)*2 + half] = hs;
                }
            }
        }
        __syncthreads();

        // QK^T: warp tile 16 x 64
        float sacc[8][4];
        #pragma unroll
        for (int i = 0; i < 8; i++) for (int r = 0; r < 4; r++) sacc[i][r] = 0.f;
        #pragma unroll
        for (int ks = 0; ks < 2; ks++) {
            unsigned afb[4], afs[4];
            ldA<136>(afb, Qb, ks*8 + t, m0 + g);
            ldA<136>(afs, Qs, ks*8 + t, m0 + g);
            #pragma unroll
            for (int nt = 0; nt < 8; nt++) {
                unsigned bb[2], bs[2];
                ldB<72>(bb, Kb, ks*8 + t, nt*8 + g);
                ldB<72>(bs, Ks, ks*8 + t, nt*8 + g);
                mma3(sacc[nt], afb, afs, bb, bs);
            }
        }

        // exp(score*scale + mask)  [no max subtraction: scores bounded]
        #pragma unroll
        for (int nt = 0; nt < 8; nt++) {
            float2 mk0 = *(const float2*)(mbase + n0 + nt*8 + 2*t);
            float2 mk1 = *(const float2*)(mbase + 8*1024 + n0 + nt*8 + 2*t);
            float e0 = __expf(fmaf(sacc[nt][0], scale, mk0.x));
            float e1 = __expf(fmaf(sacc[nt][1], scale, mk0.y));
            float e2 = __expf(fmaf(sacc[nt][2], scale, mk1.x));
            float e3 = __expf(fmaf(sacc[nt][3], scale, mk1.y));
            rs0 += e0 + e1; rs1 += e2 + e3;
            sacc[nt][0] = e0; sacc[nt][1] = e1; sacc[nt][2] = e2; sacc[nt][3] = e3;
        }

        // PV: C-fragments of P reinterpreted as A-fragments (k = n)
        #pragma unroll
        for (int kt = 0; kt < 4; kt++) {
            unsigned ab[4], as_[4];
            split_pack(sacc[2*kt][0],   sacc[2*kt][1],   ab[0], as_[0]);
            split_pack(sacc[2*kt][2],   sacc[2*kt][3],   ab[1], as_[1]);
            split_pack(sacc[2*kt+1][0], sacc[2*kt+1][1], ab[2], as_[2]);
            split_pack(sacc[2*kt+1][2], sacc[2*kt+1][3], ab[3], as_[3]);
            #pragma unroll
            for (int dt = 0; dt < 4; dt++) {
                unsigned bb[2], bs[2];
                bb[0] = Vb[kt*8 + t][dt*8 + g]; bb[1] = Vb[kt*8 + t + 4][dt*8 + g];
                bs[0] = Vs[kt*8 + t][dt*8 + g]; bs[1] = Vs[kt*8 + t + 4][dt*8 + g];
                mma3(oacc[dt], ab, as_, bb, bs);
            }
        }
        __syncthreads();
    }

    // rowsums: reduce over quad (rows fully warp-owned — no atomics)
    rs0 += __shfl_xor_sync(0xffffffffu, rs0, 1);
    rs0 += __shfl_xor_sync(0xffffffffu, rs0, 2);
    rs1 += __shfl_xor_sync(0xffffffffu, rs1, 1);
    rs1 += __shfl_xor_sync(0xffffffffu, rs1, 2);
    const float inv0 = 1.f / rs0, inv1 = 1.f / rs1;

    float* op = g_attn + ((size_t)b*256 + p0 + m0 + g)*512 + h*32;
    #pragma unroll
    for (int dt = 0; dt < 4; dt++) {
        float2 o0; o0.x = oacc[dt][0]*inv0; o0.y = oacc[dt][1]*inv0;
        float2 o1; o1.x = oacc[dt][2]*inv1; o1.y = oacc[dt][3]*inv1;
        *(float2*)(op + dt*8 + 2*t) = o0;
        *(float2*)(op + 8*512 + dt*8 + 2*t) = o1;
    }
}

// ---------------------------------------------------------------------------
// Pointer GEMM bf16x3 + tanh-clip softmax numerator (unchanged from R3)
// ---------------------------------------------------------------------------
__global__ __launch_bounds__(256) void pointer_k(const float* __restrict__ shk,
                                                 const float* __restrict__ mask,
                                                 float* __restrict__ out)
{
    __shared__ unsigned Ab[16][136], As[16][136], Bb[16][136], Bs[16][136];
    const int tid = threadIdx.x, lane = tid & 31;
    const int g = lane >> 2, t = lane & 3, wid = tid >> 5;
    const int wm = wid >> 2, wn = wid & 3;
    const int b = blockIdx.z, pblk = blockIdx.y * 128, nblk = blockIdx.x * 128;
    const int lrow = tid >> 1, lcg = (tid & 1) * 16;

    const float* Ap = g_mh + ((size_t)b*256 + pblk + lrow)*512 + lcg;
    const float* Bp = shk + (size_t)b*512*1024 + nblk + (tid & 31)*4;
    const int kplo = wid;

    float acc[4][4][4];
    #pragma unroll
    for (int i = 0; i < 4; i++) for (int j = 0; j < 4; j++) for (int r = 0; r < 4; r++)
        acc[i][j][r] = 0.f;

    float4 ar[4], br[2][2];
    #pragma unroll
    for (int c = 0; c < 4; c++) ar[c] = *(const float4*)(Ap + c*4);
    #pragma unroll
    for (int j = 0; j < 2; j++) {
        br[j][0] = *(const float4*)(Bp + (size_t)(2*(kplo + j*8))*1024);
        br[j][1] = *(const float4*)(Bp + (size_t)(2*(kplo + j*8) + 1)*1024);
    }

    for (int k0 = 0; k0 < 512; k0 += 32) {
        #pragma unroll
        for (int c = 0; c < 4; c++) {
            int kp = (lcg + c*4) >> 1; unsigned bb, ss;
            split_pack(ar[c].x, ar[c].y, bb, ss); Ab[kp][lrow] = bb; As[kp][lrow] = ss;
            split_pack(ar[c].z, ar[c].w, bb, ss); Ab[kp+1][lrow] = bb; As[kp+1][lrow] = ss;
        }
        #pragma unroll
        for (int j = 0; j < 2; j++) {
            const int kp = kplo + j*8, n4 = (tid & 31)*4;
            unsigned pb[4], ps[4];
            split_pack(br[j][0].x, br[j][1].x, pb[0], ps[0]);
            split_pack(br[j][0].y, br[j][1].y, pb[1], ps[1]);
            split_pack(br[j][0].z, br[j][1].z, pb[2], ps[2]);
            split_pack(br[j][0].w, br[j][1].w, pb[3], ps[3]);
            *(uint4*)&Bb[kp][n4] = *(uint4*)pb;
            *(uint4*)&Bs[kp][n4] = *(uint4*)ps;
        }
        __syncthreads();
        if (k0 + 32 < 512) {
            #pragma unroll
            for (int c = 0; c < 4; c++) ar[c] = *(const float4*)(Ap + k0 + 32 + c*4);
            #pragma unroll
            for (int j = 0; j < 2; j++) {
                br[j][0] = *(const float4*)(Bp + (size_t)(k0 + 32 + 2*(kplo + j*8))*1024);
                br[j][1] = *(const float4*)(Bp + (size_t)(k0 + 32 + 2*(kplo + j*8) + 1)*1024);
            }
        }
        #pragma unroll
        for (int ks = 0; ks < 2; ks++) {
            const int kb = ks * 8;
            unsigned afb[4][4], afs[4][4], bfb[4][2], bfs[4][2];
            #pragma unroll
            for (int mt = 0; mt < 4; mt++) {
                ldA<136>(afb[mt], Ab, kb + t, wm*64 + mt*16 + g);
                ldA<136>(afs[mt], As, kb + t, wm*64 + mt*16 + g);
            }
            #pragma unroll
            for (int nt = 0; nt < 4; nt++) {
                ldB<136>(bfb[nt], Bb, kb + t, wn*32 + nt*8 + g);
                ldB<136>(bfs[nt], Bs, kb + t, wn*32 + nt*8 + g);
            }
            #pragma unroll
            for (int mt = 0; mt < 4; mt++)
                #pragma unroll
                for (int nt = 0; nt < 4; nt++)
                    mma3(acc[mt][nt], afb[mt], afs[mt], bfb[nt], bfs[nt]);
        }
        __syncthreads();
    }

    const float invE = 0.04419417382415922f;
    #pragma unroll
    for (int mt = 0; mt < 4; mt++) {
        float rsl[2] = {0.f, 0.f};
        #pragma unroll
        for (int rr = 0; rr < 2; rr++) {
            const int p = pblk + wm*64 + mt*16 + g + rr*8;
            #pragma unroll
            for (int nt = 0; nt < 4; nt++) {
                const int n = nblk + wn*32 + nt*8 + 2*t;
                size_t oi = ((size_t)b*256 + p)*1024 + n;
                float2 mk = *(const float2*)(mask + oi);
                float e0 = __expf(10.f*tanhf(acc[mt][nt][rr*2]  *invE) + mk.x);
                float e1 = __expf(10.f*tanhf(acc[mt][nt][rr*2+1]*invE) + mk.y);
                rsl[rr] += e0 + e1;
                float2 o; o.x = e0; o.y = e1;
                *(float2*)(out + oi) = o;
            }
        }
        #pragma unroll
        for (int rr = 0; rr < 2; rr++) {
            float v = rsl[rr];
            v += __shfl_xor_sync(0xffffffffu, v, 1);
            v += __shfl_xor_sync(0xffffffffu, v, 2);
            if (t == 0)
                atomicAdd(&g_rowsum[b*256 + pblk + wm*64 + mt*16 + g + rr*8], v);
        }
    }
}

// ---------------------------------------------------------------------------
__global__ void zero_rowsum_k()
{
    int i = blockIdx.x * blockDim.x + threadIdx.x;
    if (i < Bn*Pn) g_rowsum[i] = 0.f;
}

__global__ void normalize_k(float* __restrict__ out)
{
    int i = blockIdx.x * blockDim.x + threadIdx.x;
    size_t i4 = (size_t)i * 4;
    int row = (int)(i4 >> 10);
    float inv = 1.f / g_rowsum[row];
    float4 v = *(float4*)&out[i4];
    v.x *= inv; v.y *= inv; v.z *= inv; v.w *= inv;
    *(float4*)&out[i4] = v;
}

// ---------------------------------------------------------------------------
extern "C" void kernel_launch(void* const* d_in, const int* in_sizes, int n_in,
                              void* d_out, int out_size)
{
    const float* enc  = (const float*)d_in[0];
    const float* mask = (const float*)d_in[1];
    const float* qf   = (const float*)d_in[2];
    const float* kmat = (const float*)d_in[3];
    const float* vmat = (const float*)d_in[4];
    const float* shk  = (const float*)d_in[5];
    const float* Wq   = (const float*)d_in[6];
    const float* Wc   = (const float*)d_in[7];
    float* out = (float*)d_out;

    float* gq; cudaGetSymbolAddress((void**)&gq, g_q);
    float* ga; cudaGetSymbolAddress((void**)&ga, g_attn);
    float* gm; cudaGetSymbolAddress((void**)&gm, g_mh);

    zero_rowsum_k<<<32, 256>>>();
    gemm_k<0><<<dim3(4, 64), 256>>>(enc, Wq, qf, gq);
    attn_k<<<dim3(512, 2), 256>>>(kmat, vmat, mask);
    gemm_k<1><<<dim3(4, 64), 256>>>(ga, Wc, qf, gm);
    pointer_k<<<dim3(8, 2, 32), 256>>>(shk, mask, out);
    normalize_k<<<8192, 256>>>(out);
}

// round 5
// speedup vs baseline: 6.7042x; 1.1459x over previous
#include <cuda_runtime.h>
#include <cuda_bf16.h>
#include <math.h>

#define Bn 32
#define Pn 256
#define Nn 1024
#define En 512
#define Hn 16
#define Dn 32

// fp32 scratch
__device__ float g_q[Bn*Hn*Pn*Dn];
__device__ float g_rowsum[Bn*Pn];
// pre-split bf16 operand arrays (uint = 2 packed bf16 along k/n)
__device__ unsigned g_encb[8192*256],  g_encs[8192*256];
__device__ unsigned g_Wqb[512*256],    g_Wqs[512*256];
__device__ unsigned g_Wcb[512*256],    g_Wcs[512*256];
__device__ unsigned g_attnb[8192*256], g_attns[8192*256];
__device__ unsigned g_mhb[8192*256],   g_mhs[8192*256];
__device__ unsigned g_shkb[32*512*512], g_shks[32*512*512];

// ---- bf16x3 helpers -------------------------------------------------------
__device__ __forceinline__ void split_pack(float x0, float x1, unsigned &b, unsigned &s) {
    __nv_bfloat16 b0 = __float2bfloat16(x0), b1 = __float2bfloat16(x1);
    __nv_bfloat16 s0 = __float2bfloat16(x0 - __bfloat162float(b0));
    __nv_bfloat16 s1 = __float2bfloat16(x1 - __bfloat162float(b1));
    b = ((unsigned)__bfloat16_as_ushort(b1) << 16) | (unsigned)__bfloat16_as_ushort(b0);
    s = ((unsigned)__bfloat16_as_ushort(s1) << 16) | (unsigned)__bfloat16_as_ushort(s0);
}

__device__ __forceinline__ void mma16816(float* c, const unsigned* a, unsigned b0, unsigned b1) {
    asm("mma.sync.aligned.m16n8k16.row.col.f32.bf16.bf16.f32 "
        "{%0,%1,%2,%3}, {%4,%5,%6,%7}, {%8,%9}, {%0,%1,%2,%3};"
        : "+f"(c[0]), "+f"(c[1]), "+f"(c[2]), "+f"(c[3])
        : "r"(a[0]), "r"(a[1]), "r"(a[2]), "r"(a[3]), "r"(b0), "r"(b1));
}
__device__ __forceinline__ void mma3(float* c, const unsigned* ab, const unsigned* as,
                                     const unsigned* bb, const unsigned* bs) {
    mma16816(c, as, bb[0], bb[1]);
    mma16816(c, ab, bs[0], bs[1]);
    mma16816(c, ab, bb[0], bb[1]);
}
template<int STR>
__device__ __forceinline__ void ldA(unsigned f[4], const unsigned (*S)[STR], int kpt, int mg) {
    f[0] = S[kpt][mg]; f[1] = S[kpt][mg+8]; f[2] = S[kpt+4][mg]; f[3] = S[kpt+4][mg+8];
}
template<int STR>
__device__ __forceinline__ void ldB(unsigned f[2], const unsigned (*S)[STR], int kpt, int ng) {
    f[0] = S[kpt][ng]; f[1] = S[kpt+4][ng];
}
__device__ __forceinline__ void ldm4(unsigned f[4], unsigned addr) {
    asm volatile("ldmatrix.sync.aligned.m8n8.x4.shared.b16 {%0,%1,%2,%3}, [%4];"
        : "=r"(f[0]), "=r"(f[1]), "=r"(f[2]), "=r"(f[3]) : "r"(addr));
}
__device__ __forceinline__ void ldm4t(unsigned f[4], unsigned addr) {
    asm volatile("ldmatrix.sync.aligned.m8n8.x4.trans.shared.b16 {%0,%1,%2,%3}, [%4];"
        : "=r"(f[0]), "=r"(f[1]), "=r"(f[2]), "=r"(f[3]) : "r"(addr));
}
__device__ __forceinline__ void cpa16(unsigned smem, const void* g) {
    asm volatile("cp.async.cg.shared.global [%0], [%1], 16;" :: "r"(smem), "l"(g));
}

// ---------------------------------------------------------------------------
// split kernel: fp32 -> (big,small) bf16 pair arrays
// ---------------------------------------------------------------------------
__global__ void split_k(const float* __restrict__ in, unsigned* __restrict__ ob,
                        unsigned* __restrict__ os, int n4)
{
    int i = blockIdx.x * blockDim.x + threadIdx.x;
    if (i < n4) {
        float4 v = *(const float4*)(in + (size_t)i * 4);
        unsigned b0, s0, b1, s1;
        split_pack(v.x, v.y, b0, s0);
        split_pack(v.z, v.w, b1, s1);
        ob[2*i] = b0; ob[2*i+1] = b1;
        os[2*i] = s0; os[2*i+1] = s1;
    }
}

// ---------------------------------------------------------------------------
// Dense GEMM (pre-split bf16): C = A[M,512] @ W[N,512]^T
// 128x128 tile, kstep 32, cp.async 2-stage, ldmatrix fragments.
// EPI 0: scatter g_q + qf.  EPI 1: write split bf16 (Cb,Cs).
// ---------------------------------------------------------------------------
template<int EPI>
__global__ __launch_bounds__(256, 2) void gemm_k(
    const unsigned* __restrict__ Agb, const unsigned* __restrict__ Ags,
    const unsigned* __restrict__ Bgb, const unsigned* __restrict__ Bgs,
    const float* __restrict__ qf, float* __restrict__ Cout,
    unsigned* __restrict__ Cb, unsigned* __restrict__ Cs)
{
    extern __shared__ unsigned smd[];
    const unsigned sbase = (unsigned)__cvta_generic_to_shared(smd);
    const int tid = threadIdx.x, lane = tid & 31, w = tid >> 5;
    const int g = lane >> 2, t = lane & 3;
    const int wm = w >> 2, wn = w & 3;
    const int mblk = blockIdx.y * 128, nblk = blockIdx.x * 128;

    float acc[4][4][4];
    #pragma unroll
    for (int i = 0; i < 4; i++) for (int j = 0; j < 4; j++) for (int r = 0; r < 4; r++)
        acc[i][j][r] = 0.f;

    auto stage = [&](int kt, int buf) {
        const int ku = kt * 16;
        #pragma unroll
        for (int i = 0; i < 8; i++) {
            int c = tid + i * 256;
            int arr = c >> 9, j = c & 511;
            int row = j >> 2, c16 = j & 3;
            const unsigned* gp = (arr == 0) ? Agb : (arr == 1) ? Ags : (arr == 2) ? Bgb : Bgs;
            int rb = (arr < 2) ? mblk : nblk;
            cpa16(sbase + buf * 40960 + arr * 10240 + row * 80 + c16 * 16,
                  gp + (size_t)(rb + row) * 256 + ku + c16 * 4);
        }
        asm volatile("cp.async.commit_group;");
    };

    stage(0, 0);
    for (int kt = 0; kt < 16; kt++) {
        if (kt < 15) { stage(kt + 1, (kt + 1) & 1); asm volatile("cp.async.wait_group 1;"); }
        else         { asm volatile("cp.async.wait_group 0;"); }
        __syncthreads();
        const unsigned sb = sbase + (kt & 1) * 40960;
        #pragma unroll
        for (int ks = 0; ks < 2; ks++) {
            unsigned afb[4][4], afs[4][4];
            #pragma unroll
            for (int mt = 0; mt < 4; mt++) {
                unsigned ad = sb + (wm*64 + mt*16 + (lane & 15)) * 80 + (lane >> 4) * 16 + ks * 32;
                ldm4(afb[mt], ad);
                ldm4(afs[mt], ad + 10240);
            }
            #pragma unroll
            for (int ntp = 0; ntp < 2; ntp++) {
                unsigned bd = sb + 20480
                    + (wn*32 + ntp*16 + (lane & 7) + ((lane >> 4) & 1) * 8) * 80
                    + ((lane >> 3) & 1) * 16 + ks * 32;
                unsigned bb[4], bs2[4];
                ldm4(bb, bd); ldm4(bs2, bd + 10240);
                #pragma unroll
                for (int mt = 0; mt < 4; mt++) {
                    mma3(acc[mt][2*ntp],   afb[mt], afs[mt], bb,     bs2);
                    mma3(acc[mt][2*ntp+1], afb[mt], afs[mt], bb + 2, bs2 + 2);
                }
            }
        }
        __syncthreads();
    }

    #pragma unroll
    for (int mt = 0; mt < 4; mt++)
        #pragma unroll
        for (int nt = 0; nt < 4; nt++)
            #pragma unroll
            for (int rr = 0; rr < 2; rr++) {
                int m = mblk + wm*64 + mt*16 + g + rr*8;
                int n = nblk + wn*32 + nt*8 + 2*t;
                float v0 = acc[mt][nt][rr*2], v1 = acc[mt][nt][rr*2+1];
                if (EPI == 0) {
                    int b = m >> 8, p = m & 255, h = n >> 5, d = n & 31;
                    size_t idx = (((size_t)b*16 + h)*256 + p)*32 + d;
                    float2 q2 = *(const float2*)(qf + idx);
                    float2 o; o.x = v0 + q2.x; o.y = v1 + q2.y;
                    *(float2*)(Cout + idx) = o;
                } else {
                    unsigned ub, us;
                    split_pack(v0, v1, ub, us);
                    size_t ui = (size_t)m * 256 + (n >> 1);
                    Cb[ui] = ub; Cs[ui] = us;
                }
            }
}

// ---------------------------------------------------------------------------
// Fused attention (R4 structure; epilogue writes split bf16 for gemm<1>)
// ---------------------------------------------------------------------------
__global__ __launch_bounds__(256, 2) void attn_k(const float* __restrict__ kmat,
                                                 const float* __restrict__ vmat,
                                                 const float* __restrict__ mask)
{
    __shared__ unsigned Qb[16][136], Qs[16][136];
    __shared__ unsigned Kb[16][72],  Ks[16][72];
    __shared__ unsigned Vb[32][40],  Vs[32][40];

    const int bh = blockIdx.x, b = bh >> 4, h = bh & 15;
    const int p0 = blockIdx.y * 128;
    const int tid = threadIdx.x, lane = tid & 31;
    const int g = lane >> 2, t = lane & 3, w = tid >> 5;
    const int m0 = w * 16;
    const float scale = 0.1767766952966369f;

    {
        const int lrow = tid >> 1, lcg = (tid & 1) * 16;
        const float* qp = g_q + ((size_t)bh*256 + p0 + lrow)*32 + lcg;
        #pragma unroll
        for (int c = 0; c < 4; c++) {
            float4 v = *(const float4*)(qp + c*4);
            int kp = (lcg + c*4) >> 1; unsigned bb, ss;
            split_pack(v.x, v.y, bb, ss); Qb[kp][lrow] = bb; Qs[kp][lrow] = ss;
            split_pack(v.z, v.w, bb, ss); Qb[kp+1][lrow] = bb; Qs[kp+1][lrow] = ss;
        }
    }

    const int srow = tid & 63;
    const int sd = ((tid >> 6) & 1) * 16;
    const bool doV = tid >= 128;
    const float* kb0 = kmat + (size_t)bh * (1024*32);
    const float* vb0 = vmat + (size_t)bh * (1024*32);
    const float* mbase = mask + ((size_t)b*256 + p0 + m0 + g)*1024;

    float oacc[4][4];
    #pragma unroll
    for (int i = 0; i < 4; i++) for (int j = 0; j < 4; j++) oacc[i][j] = 0.f;
    float rs0 = 0.f, rs1 = 0.f;

    for (int n0 = 0; n0 < 1024; n0 += 64) {
        if (!doV) {
            const float* kp_ = kb0 + (size_t)(n0 + srow)*32 + sd;
            #pragma unroll
            for (int c = 0; c < 4; c++) {
                float4 v = *(const float4*)(kp_ + c*4);
                int kp = (sd + c*4) >> 1; unsigned bb, ss;
                split_pack(v.x, v.y, bb, ss); Kb[kp][srow] = bb; Ks[kp][srow] = ss;
                split_pack(v.z, v.w, bb, ss); Kb[kp+1][srow] = bb; Ks[kp+1][srow] = ss;
            }
        } else {
            const float* vp_ = vb0 + (size_t)(n0 + srow)*32 + sd;
            __nv_bfloat16* Vbh = (__nv_bfloat16*)Vb;
            __nv_bfloat16* Vsh = (__nv_bfloat16*)Vs;
            const int np = srow >> 1, half = srow & 1;
            #pragma unroll
            for (int c = 0; c < 4; c++) {
                float4 v = *(const float4*)(vp_ + c*4);
                float vv[4] = {v.x, v.y, v.z, v.w};
                #pragma unroll
                for (int i = 0; i < 4; i++) {
                    int d = sd + c*4 + i;
                    __nv_bfloat16 hb = __float2bfloat16(vv[i]);
                    __nv_bfloat16 hs = __float2bfloat16(vv[i] - __bfloat162float(hb));
                    Vbh[(np*40 + d)*2 + half] = hb;
                    Vsh[(np*40 + d)*2 + half] = hs;
                }
            }
        }
        __syncthreads();

        float sacc[8][4];
        #pragma unroll
        for (int i = 0; i < 8; i++) for (int r = 0; r < 4; r++) sacc[i][r] = 0.f;
        #pragma unroll
        for (int ks = 0; ks < 2; ks++) {
            unsigned afb[4], afs[4];
            ldA<136>(afb, Qb, ks*8 + t, m0 + g);
            ldA<136>(afs, Qs, ks*8 + t, m0 + g);
            #pragma unroll
            for (int nt = 0; nt < 8; nt++) {
                unsigned bb[2], bs[2];
                ldB<72>(bb, Kb, ks*8 + t, nt*8 + g);
                ldB<72>(bs, Ks, ks*8 + t, nt*8 + g);
                mma3(sacc[nt], afb, afs, bb, bs);
            }
        }

        #pragma unroll
        for (int nt = 0; nt < 8; nt++) {
            float2 mk0 = *(const float2*)(mbase + n0 + nt*8 + 2*t);
            float2 mk1 = *(const float2*)(mbase + 8*1024 + n0 + nt*8 + 2*t);
            float e0 = __expf(fmaf(sacc[nt][0], scale, mk0.x));
            float e1 = __expf(fmaf(sacc[nt][1], scale, mk0.y));
            float e2 = __expf(fmaf(sacc[nt][2], scale, mk1.x));
            float e3 = __expf(fmaf(sacc[nt][3], scale, mk1.y));
            rs0 += e0 + e1; rs1 += e2 + e3;
            sacc[nt][0] = e0; sacc[nt][1] = e1; sacc[nt][2] = e2; sacc[nt][3] = e3;
        }

        #pragma unroll
        for (int kt = 0; kt < 4; kt++) {
            unsigned ab[4], as_[4];
            split_pack(sacc[2*kt][0],   sacc[2*kt][1],   ab[0], as_[0]);
            split_pack(sacc[2*kt][2],   sacc[2*kt][3],   ab[1], as_[1]);
            split_pack(sacc[2*kt+1][0], sacc[2*kt+1][1], ab[2], as_[2]);
            split_pack(sacc[2*kt+1][2], sacc[2*kt+1][3], ab[3], as_[3]);
            #pragma unroll
            for (int dt = 0; dt < 4; dt++) {
                unsigned bb[2], bs[2];
                bb[0] = Vb[kt*8 + t][dt*8 + g]; bb[1] = Vb[kt*8 + t + 4][dt*8 + g];
                bs[0] = Vs[kt*8 + t][dt*8 + g]; bs[1] = Vs[kt*8 + t + 4][dt*8 + g];
                mma3(oacc[dt], ab, as_, bb, bs);
            }
        }
        __syncthreads();
    }

    rs0 += __shfl_xor_sync(0xffffffffu, rs0, 1);
    rs0 += __shfl_xor_sync(0xffffffffu, rs0, 2);
    rs1 += __shfl_xor_sync(0xffffffffu, rs1, 1);
    rs1 += __shfl_xor_sync(0xffffffffu, rs1, 2);
    const float inv0 = 1.f / rs0, inv1 = 1.f / rs1;

    const size_t row0 = (size_t)b*256 + p0 + m0 + g;
    #pragma unroll
    for (int dt = 0; dt < 4; dt++) {
        unsigned ub, us;
        int cu = (h*32 + dt*8 + 2*t) >> 1;
        split_pack(oacc[dt][0]*inv0, oacc[dt][1]*inv0, ub, us);
        g_attnb[row0*256 + cu] = ub; g_attns[row0*256 + cu] = us;
        split_pack(oacc[dt][2]*inv1, oacc[dt][3]*inv1, ub, us);
        g_attnb[(row0 + 8)*256 + cu] = ub; g_attns[(row0 + 8)*256 + cu] = us;
    }
}

// ---------------------------------------------------------------------------
// Pointer GEMM (pre-split) + tanh-clip softmax numerator. grid (8,2,32).
// ---------------------------------------------------------------------------
__global__ __launch_bounds__(256, 2) void pointer_k(const float* __restrict__ mask,
                                                    float* __restrict__ out)
{
    extern __shared__ unsigned smd[];
    const unsigned sbase = (unsigned)__cvta_generic_to_shared(smd);
    const int tid = threadIdx.x, lane = tid & 31, w = tid >> 5;
    const int g = lane >> 2, t = lane & 3;
    const int wm = w >> 2, wn = w & 3;
    const int b = blockIdx.z, pblk = blockIdx.y * 128, nblk = blockIdx.x * 128;
    const int mrow0 = b * 256 + pblk;
    const int nu0 = blockIdx.x * 64;

    float acc[4][4][4];
    #pragma unroll
    for (int i = 0; i < 4; i++) for (int j = 0; j < 4; j++) for (int r = 0; r < 4; r++)
        acc[i][j][r] = 0.f;

    auto stage = [&](int kt, int buf) {
        const int ku = kt * 16, k0 = kt * 32;
        #pragma unroll
        for (int i = 0; i < 8; i++) {
            int c = tid + i * 256;
            if (c < 1024) {
                int arr = c >> 9, j = c & 511;
                int row = j >> 2, c16 = j & 3;
                const unsigned* gp = arr ? g_mhs : g_mhb;
                cpa16(sbase + buf * 37888 + arr * 10240 + row * 80 + c16 * 16,
                      gp + (size_t)(mrow0 + row) * 256 + ku + c16 * 4);
            } else {
                int cb = c - 1024;
                int arr = cb >> 9, j = cb & 511;
                int row = j >> 4, c16 = j & 15;
                const unsigned* gp = arr ? g_shks : g_shkb;
                cpa16(sbase + buf * 37888 + 20480 + arr * 8704 + row * 272 + c16 * 16,
                      gp + ((size_t)(b * 512 + k0 + row)) * 512 + nu0 + c16 * 4);
            }
        }
        asm volatile("cp.async.commit_group;");
    };

    stage(0, 0);
    for (int kt = 0; kt < 16; kt++) {
        if (kt < 15) { stage(kt + 1, (kt + 1) & 1); asm volatile("cp.async.wait_group 1;"); }
        else         { asm volatile("cp.async.wait_group 0;"); }
        __syncthreads();
        const unsigned sb = sbase + (kt & 1) * 37888;
        #pragma unroll
        for (int ks = 0; ks < 2; ks++) {
            unsigned afb[4][4], afs[4][4];
            #pragma unroll
            for (int mt = 0; mt < 4; mt++) {
                unsigned ad = sb + (wm*64 + mt*16 + (lane & 15)) * 80 + (lane >> 4) * 16 + ks * 32;
                ldm4(afb[mt], ad);
                ldm4(afs[mt], ad + 10240);
            }
            #pragma unroll
            for (int ntp = 0; ntp < 2; ntp++) {
                unsigned bd = sb + 20480 + ((lane & 15) + ks * 16) * 272
                            + (wn*32 + ntp*16) * 2 + (lane >> 4) * 16;
                unsigned bb[4], bs2[4];
                ldm4t(bb, bd); ldm4t(bs2, bd + 8704);
                #pragma unroll
                for (int mt = 0; mt < 4; mt++) {
                    mma3(acc[mt][2*ntp],   afb[mt], afs[mt], bb,     bs2);
                    mma3(acc[mt][2*ntp+1], afb[mt], afs[mt], bb + 2, bs2 + 2);
                }
            }
        }
        __syncthreads();
    }

    const float invE = 0.04419417382415922f;
    #pragma unroll
    for (int mt = 0; mt < 4; mt++) {
        float rsl[2] = {0.f, 0.f};
        #pragma unroll
        for (int rr = 0; rr < 2; rr++) {
            const int p = pblk + wm*64 + mt*16 + g + rr*8;
            #pragma unroll
            for (int nt = 0; nt < 4; nt++) {
                const int n = nblk + wn*32 + nt*8 + 2*t;
                size_t oi = ((size_t)b*256 + p)*1024 + n;
                float2 mk = *(const float2*)(mask + oi);
                float e0 = __expf(10.f*tanhf(acc[mt][nt][rr*2]  *invE) + mk.x);
                float e1 = __expf(10.f*tanhf(acc[mt][nt][rr*2+1]*invE) + mk.y);
                rsl[rr] += e0 + e1;
                float2 o; o.x = e0; o.y = e1;
                *(float2*)(out + oi) = o;
            }
        }
        #pragma unroll
        for (int rr = 0; rr < 2; rr++) {
            float v = rsl[rr];
            v += __shfl_xor_sync(0xffffffffu, v, 1);
            v += __shfl_xor_sync(0xffffffffu, v, 2);
            if (t == 0)
                atomicAdd(&g_rowsum[b*256 + pblk + wm*64 + mt*16 + g + rr*8], v);
        }
    }
}

// ---------------------------------------------------------------------------
__global__ void zero_rowsum_k()
{
    int i = blockIdx.x * blockDim.x + threadIdx.x;
    if (i < Bn*Pn) g_rowsum[i] = 0.f;
}

__global__ void normalize_k(float* __restrict__ out)
{
    int i = blockIdx.x * blockDim.x + threadIdx.x;
    size_t i4 = (size_t)i * 4;
    int row = (int)(i4 >> 10);
    float inv = 1.f / g_rowsum[row];
    float4 v = *(float4*)&out[i4];
    v.x *= inv; v.y *= inv; v.z *= inv; v.w *= inv;
    *(float4*)&out[i4] = v;
}

// ---------------------------------------------------------------------------
extern "C" void kernel_launch(void* const* d_in, const int* in_sizes, int n_in,
                              void* d_out, int out_size)
{
    const float* enc  = (const float*)d_in[0];
    const float* mask = (const float*)d_in[1];
    const float* qf   = (const float*)d_in[2];
    const float* kmat = (const float*)d_in[3];
    const float* vmat = (const float*)d_in[4];
    const float* shk  = (const float*)d_in[5];
    const float* Wq   = (const float*)d_in[6];
    const float* Wc   = (const float*)d_in[7];
    float* out = (float*)d_out;

    float *gq;
    unsigned *encb, *encs, *wqb, *wqs, *wcb, *wcs, *attnb, *attns, *mhb, *mhs, *shkb, *shks;
    cudaGetSymbolAddress((void**)&gq,   g_q);
    cudaGetSymbolAddress((void**)&encb, g_encb);  cudaGetSymbolAddress((void**)&encs, g_encs);
    cudaGetSymbolAddress((void**)&wqb,  g_Wqb);   cudaGetSymbolAddress((void**)&wqs,  g_Wqs);
    cudaGetSymbolAddress((void**)&wcb,  g_Wcb);   cudaGetSymbolAddress((void**)&wcs,  g_Wcs);
    cudaGetSymbolAddress((void**)&attnb,g_attnb); cudaGetSymbolAddress((void**)&attns,g_attns);
    cudaGetSymbolAddress((void**)&mhb,  g_mhb);   cudaGetSymbolAddress((void**)&mhs,  g_mhs);
    cudaGetSymbolAddress((void**)&shkb, g_shkb);  cudaGetSymbolAddress((void**)&shks, g_shks);

    cudaFuncSetAttribute(gemm_k<0>, cudaFuncAttributeMaxDynamicSharedMemorySize, 81920);
    cudaFuncSetAttribute(gemm_k<1>, cudaFuncAttributeMaxDynamicSharedMemorySize, 81920);
    cudaFuncSetAttribute(pointer_k, cudaFuncAttributeMaxDynamicSharedMemorySize, 75776);

    zero_rowsum_k<<<32, 256>>>();
    split_k<<<4096, 256>>>(enc, encb, encs, 1048576);
    split_k<<<256, 256>>>(Wq, wqb, wqs, 65536);
    split_k<<<256, 256>>>(Wc, wcb, wcs, 65536);
    split_k<<<16384, 256>>>(shk, shkb, shks, 4194304);

    gemm_k<0><<<dim3(4, 64), 256, 81920>>>(encb, encs, wqb, wqs, qf, gq, nullptr, nullptr);
    attn_k<<<dim3(512, 2), 256>>>(kmat, vmat, mask);
    gemm_k<1><<<dim3(4, 64), 256, 81920>>>(attnb, attns, wcb, wcs, nullptr, nullptr, mhb, mhs);
    pointer_k<<<dim3(8, 2, 32), 256, 75776>>>(mask, out);
    normalize_k<<<8192, 256>>>(out);
}

// round 6
// speedup vs baseline: 7.2557x; 1.0823x over previous
#include <cuda_runtime.h>
#include <cuda_bf16.h>
#include <math.h>

#define Bn 32
#define Pn 256
#define Nn 1024
#define En 512
#define Hn 16
#define Dn 32

__device__ float g_rowsum[Bn*Pn];
// pre-split bf16 operand arrays (uint = 2 packed bf16 along k/n/d)
__device__ unsigned g_encb[8192*256],  g_encs[8192*256];
__device__ unsigned g_Wqb[512*256],    g_Wqs[512*256];
__device__ unsigned g_Wcb[512*256],    g_Wcs[512*256];
__device__ unsigned g_attnb[8192*256], g_attns[8192*256];
__device__ unsigned g_mhb[8192*256],   g_mhs[8192*256];
__device__ unsigned g_shkb[32*512*512], g_shks[32*512*512];
__device__ unsigned g_qb[Bn*Hn*Pn*16],  g_qs[Bn*Hn*Pn*16];   // [bh,p,kpair]
__device__ unsigned g_kb[Bn*Hn*Nn*16],  g_ks[Bn*Hn*Nn*16];   // [bh,n,dpair]
__device__ unsigned g_vb[Bn*Hn*Nn*16],  g_vs[Bn*Hn*Nn*16];   // [bh,n,dpair]

// ---- bf16x3 helpers -------------------------------------------------------
__device__ __forceinline__ void split_pack(float x0, float x1, unsigned &b, unsigned &s) {
    __nv_bfloat16 b0 = __float2bfloat16(x0), b1 = __float2bfloat16(x1);
    __nv_bfloat16 s0 = __float2bfloat16(x0 - __bfloat162float(b0));
    __nv_bfloat16 s1 = __float2bfloat16(x1 - __bfloat162float(b1));
    b = ((unsigned)__bfloat16_as_ushort(b1) << 16) | (unsigned)__bfloat16_as_ushort(b0);
    s = ((unsigned)__bfloat16_as_ushort(s1) << 16) | (unsigned)__bfloat16_as_ushort(s0);
}

__device__ __forceinline__ void mma16816(float* c, const unsigned* a, unsigned b0, unsigned b1) {
    asm("mma.sync.aligned.m16n8k16.row.col.f32.bf16.bf16.f32 "
        "{%0,%1,%2,%3}, {%4,%5,%6,%7}, {%8,%9}, {%0,%1,%2,%3};"
        : "+f"(c[0]), "+f"(c[1]), "+f"(c[2]), "+f"(c[3])
        : "r"(a[0]), "r"(a[1]), "r"(a[2]), "r"(a[3]), "r"(b0), "r"(b1));
}
__device__ __forceinline__ void mma3(float* c, const unsigned* ab, const unsigned* as,
                                     const unsigned* bb, const unsigned* bs) {
    mma16816(c, as, bb[0], bb[1]);
    mma16816(c, ab, bs[0], bs[1]);
    mma16816(c, ab, bb[0], bb[1]);
}
__device__ __forceinline__ void ldm4(unsigned f[4], unsigned addr) {
    asm volatile("ldmatrix.sync.aligned.m8n8.x4.shared.b16 {%0,%1,%2,%3}, [%4];"
        : "=r"(f[0]), "=r"(f[1]), "=r"(f[2]), "=r"(f[3]) : "r"(addr));
}
__device__ __forceinline__ void ldm4t(unsigned f[4], unsigned addr) {
    asm volatile("ldmatrix.sync.aligned.m8n8.x4.trans.shared.b16 {%0,%1,%2,%3}, [%4];"
        : "=r"(f[0]), "=r"(f[1]), "=r"(f[2]), "=r"(f[3]) : "r"(addr));
}
__device__ __forceinline__ void cpa16(unsigned smem, const void* g) {
    asm volatile("cp.async.cg.shared.global [%0], [%1], 16;" :: "r"(smem), "l"(g));
}

// ---------------------------------------------------------------------------
// split kernel: fp32 -> (big,small) bf16 pair arrays
// ---------------------------------------------------------------------------
__global__ void split_k(const float* __restrict__ in, unsigned* __restrict__ ob,
                        unsigned* __restrict__ os, int n4)
{
    int i = blockIdx.x * blockDim.x + threadIdx.x;
    if (i < n4) {
        float4 v = *(const float4*)(in + (size_t)i * 4);
        unsigned b0, s0, b1, s1;
        split_pack(v.x, v.y, b0, s0);
        split_pack(v.z, v.w, b1, s1);
        ob[2*i] = b0; ob[2*i+1] = b1;
        os[2*i] = s0; os[2*i+1] = s1;
    }
}

// ---------------------------------------------------------------------------
// Dense GEMM (pre-split bf16): C = A[M,512] @ W[N,512]^T
// EPI 0: write split q to Cb/Cs ([bh,p,kpair]) with qf add.
// EPI 1: write split bf16 rows (Cb,Cs, row = 256 uints).
// ---------------------------------------------------------------------------
template<int EPI>
__global__ __launch_bounds__(256, 2) void gemm_k(
    const unsigned* __restrict__ Agb, const unsigned* __restrict__ Ags,
    const unsigned* __restrict__ Bgb, const unsigned* __restrict__ Bgs,
    const float* __restrict__ qf,
    unsigned* __restrict__ Cb, unsigned* __restrict__ Cs)
{
    extern __shared__ unsigned smd[];
    const unsigned sbase = (unsigned)__cvta_generic_to_shared(smd);
    const int tid = threadIdx.x, lane = tid & 31, w = tid >> 5;
    const int g = lane >> 2, t = lane & 3;
    const int wm = w >> 2, wn = w & 3;
    const int mblk = blockIdx.y * 128, nblk = blockIdx.x * 128;

    float acc[4][4][4];
    #pragma unroll
    for (int i = 0; i < 4; i++) for (int j = 0; j < 4; j++) for (int r = 0; r < 4; r++)
        acc[i][j][r] = 0.f;

    auto stage = [&](int kt, int buf) {
        const int ku = kt * 16;
        #pragma unroll
        for (int i = 0; i < 8; i++) {
            int c = tid + i * 256;
            int arr = c >> 9, j = c & 511;
            int row = j >> 2, c16 = j & 3;
            const unsigned* gp = (arr == 0) ? Agb : (arr == 1) ? Ags : (arr == 2) ? Bgb : Bgs;
            int rb = (arr < 2) ? mblk : nblk;
            cpa16(sbase + buf * 40960 + arr * 10240 + row * 80 + c16 * 16,
                  gp + (size_t)(rb + row) * 256 + ku + c16 * 4);
        }
        asm volatile("cp.async.commit_group;");
    };

    stage(0, 0);
    for (int kt = 0; kt < 16; kt++) {
        if (kt < 15) { stage(kt + 1, (kt + 1) & 1); asm volatile("cp.async.wait_group 1;"); }
        else         { asm volatile("cp.async.wait_group 0;"); }
        __syncthreads();
        const unsigned sb = sbase + (kt & 1) * 40960;
        #pragma unroll
        for (int ks = 0; ks < 2; ks++) {
            unsigned afb[4][4], afs[4][4];
            #pragma unroll
            for (int mt = 0; mt < 4; mt++) {
                unsigned ad = sb + (wm*64 + mt*16 + (lane & 15)) * 80 + (lane >> 4) * 16 + ks * 32;
                ldm4(afb[mt], ad);
                ldm4(afs[mt], ad + 10240);
            }
            #pragma unroll
            for (int ntp = 0; ntp < 2; ntp++) {
                unsigned bd = sb + 20480
                    + (wn*32 + ntp*16 + (lane & 7) + ((lane >> 4) & 1) * 8) * 80
                    + ((lane >> 3) & 1) * 16 + ks * 32;
                unsigned bb[4], bs2[4];
                ldm4(bb, bd); ldm4(bs2, bd + 10240);
                #pragma unroll
                for (int mt = 0; mt < 4; mt++) {
                    mma3(acc[mt][2*ntp],   afb[mt], afs[mt], bb,     bs2);
                    mma3(acc[mt][2*ntp+1], afb[mt], afs[mt], bb + 2, bs2 + 2);
                }
            }
        }
        __syncthreads();
    }

    #pragma unroll
    for (int mt = 0; mt < 4; mt++)
        #pragma unroll
        for (int nt = 0; nt < 4; nt++)
            #pragma unroll
            for (int rr = 0; rr < 2; rr++) {
                int m = mblk + wm*64 + mt*16 + g + rr*8;
                int n = nblk + wn*32 + nt*8 + 2*t;
                float v0 = acc[mt][nt][rr*2], v1 = acc[mt][nt][rr*2+1];
                unsigned ub, us;
                if (EPI == 0) {
                    int b = m >> 8, p = m & 255, h = n >> 5, d = n & 31;
                    size_t fidx = (((size_t)b*16 + h)*256 + p)*32 + d;
                    float2 q2 = *(const float2*)(qf + fidx);
                    split_pack(v0 + q2.x, v1 + q2.y, ub, us);
                    size_t ui = (((size_t)b*16 + h)*256 + p)*16 + (d >> 1);
                    Cb[ui] = ub; Cs[ui] = us;
                } else {
                    split_pack(v0, v1, ub, us);
                    size_t ui = (size_t)m * 256 + (n >> 1);
                    Cb[ui] = ub; Cs[ui] = us;
                }
            }
}

// ---------------------------------------------------------------------------
// Fused attention v3: pre-split Q/K/V, cp.async staging, ldmatrix fragments,
// P in registers. 40KB static smem, grid (B*H, P/128), 256 threads.
// ---------------------------------------------------------------------------
__global__ __launch_bounds__(256, 2) void attn_k(const float* __restrict__ mask)
{
    __shared__ unsigned smA[10240];   // [2 stages][Kb,Ks,Vb,Vs][64 rows x 80B]
    const unsigned sbase = (unsigned)__cvta_generic_to_shared(smA);

    const int bh = blockIdx.x, b = bh >> 4, h = bh & 15;
    const int p0 = blockIdx.y * 128;
    const int tid = threadIdx.x, lane = tid & 31;
    const int g = lane >> 2, t = lane & 3, w = tid >> 5;
    const int m0 = w * 16;
    const float scale = 0.1767766952966369f;  // 1/sqrt(32)

    // Q A-fragments once via direct LDG (layout [bh,p,kpair])
    unsigned qfb[2][4], qfs[2][4];
    {
        const size_t r0 = ((size_t)bh*256 + p0 + m0 + g) * 16;
        #pragma unroll
        for (int ks = 0; ks < 2; ks++) {
            qfb[ks][0] = g_qb[r0 + t + ks*8];        qfs[ks][0] = g_qs[r0 + t + ks*8];
            qfb[ks][1] = g_qb[r0 + 128 + t + ks*8];  qfs[ks][1] = g_qs[r0 + 128 + t + ks*8];
            qfb[ks][2] = g_qb[r0 + t + 4 + ks*8];    qfs[ks][2] = g_qs[r0 + t + 4 + ks*8];
            qfb[ks][3] = g_qb[r0 + 128 + t + 4 + ks*8]; qfs[ks][3] = g_qs[r0 + 128 + t + 4 + ks*8];
        }
    }

    const float* mbase = mask + ((size_t)b*256 + p0 + m0 + g)*1024;

    auto stage = [&](int n0, int buf) {
        #pragma unroll
        for (int i = 0; i < 4; i++) {
            int c = tid + i * 256;          // 0..1023
            int arr = c >> 8, j = c & 255;  // arr: Kb,Ks,Vb,Vs
            int row = j >> 2, c16 = j & 3;
            const unsigned* gp = (arr == 0) ? g_kb : (arr == 1) ? g_ks
                               : (arr == 2) ? g_vb : g_vs;
            cpa16(sbase + buf * 20480 + arr * 5120 + row * 80 + c16 * 16,
                  gp + ((size_t)(bh*1024 + n0 + row))*16 + c16 * 4);
        }
        asm volatile("cp.async.commit_group;");
    };

    float oacc[4][4];
    #pragma unroll
    for (int i = 0; i < 4; i++) for (int j = 0; j < 4; j++) oacc[i][j] = 0.f;
    float rs0 = 0.f, rs1 = 0.f;

    stage(0, 0);
    for (int c = 0; c < 16; c++) {
        const int n0 = c * 64;
        if (c < 15) { stage(n0 + 64, (c + 1) & 1); asm volatile("cp.async.wait_group 1;"); }
        else        { asm volatile("cp.async.wait_group 0;"); }
        __syncthreads();
        const unsigned sb = sbase + (c & 1) * 20480;

        // QK^T: 16 x 64, k = 32
        float sacc[8][4];
        #pragma unroll
        for (int i = 0; i < 8; i++) for (int r = 0; r < 4; r++) sacc[i][r] = 0.f;
        #pragma unroll
        for (int ks = 0; ks < 2; ks++) {
            #pragma unroll
            for (int nt = 0; nt < 4; nt++) {
                unsigned kd = sb + (nt*16 + (lane & 7) + ((lane >> 4) & 1) * 8) * 80
                            + ((lane >> 3) & 1) * 16 + ks * 32;
                unsigned bb[4], bs2[4];
                ldm4(bb, kd); ldm4(bs2, kd + 5120);
                mma3(sacc[2*nt],   qfb[ks], qfs[ks], bb,     bs2);
                mma3(sacc[2*nt+1], qfb[ks], qfs[ks], bb + 2, bs2 + 2);
            }
        }

        // exp(score*scale + mask)  [no max subtraction: scores bounded]
        #pragma unroll
        for (int nt = 0; nt < 8; nt++) {
            float2 mk0 = *(const float2*)(mbase + n0 + nt*8 + 2*t);
            float2 mk1 = *(const float2*)(mbase + 8*1024 + n0 + nt*8 + 2*t);
            float e0 = __expf(fmaf(sacc[nt][0], scale, mk0.x));
            float e1 = __expf(fmaf(sacc[nt][1], scale, mk0.y));
            float e2 = __expf(fmaf(sacc[nt][2], scale, mk1.x));
            float e3 = __expf(fmaf(sacc[nt][3], scale, mk1.y));
            rs0 += e0 + e1; rs1 += e2 + e3;
            sacc[nt][0] = e0; sacc[nt][1] = e1; sacc[nt][2] = e2; sacc[nt][3] = e3;
        }

        // PV: P C-frags -> A-frags in registers; V B-frags via ldmatrix.trans
        #pragma unroll
        for (int kt = 0; kt < 4; kt++) {
            unsigned ab[4], as_[4];
            split_pack(sacc[2*kt][0],   sacc[2*kt][1],   ab[0], as_[0]);
            split_pack(sacc[2*kt][2],   sacc[2*kt][3],   ab[1], as_[1]);
            split_pack(sacc[2*kt+1][0], sacc[2*kt+1][1], ab[2], as_[2]);
            split_pack(sacc[2*kt+1][2], sacc[2*kt+1][3], ab[3], as_[3]);
            #pragma unroll
            for (int dh = 0; dh < 2; dh++) {
                unsigned vd = sb + 10240 + ((lane & 15) + kt*16) * 80 + dh*32 + (lane >> 4) * 16;
                unsigned bb[4], bs2[4];
                ldm4t(bb, vd); ldm4t(bs2, vd + 5120);
                mma3(oacc[dh*2],   ab, as_, bb,     bs2);
                mma3(oacc[dh*2+1], ab, as_, bb + 2, bs2 + 2);
            }
        }
        __syncthreads();
    }

    rs0 += __shfl_xor_sync(0xffffffffu, rs0, 1);
    rs0 += __shfl_xor_sync(0xffffffffu, rs0, 2);
    rs1 += __shfl_xor_sync(0xffffffffu, rs1, 1);
    rs1 += __shfl_xor_sync(0xffffffffu, rs1, 2);
    const float inv0 = 1.f / rs0, inv1 = 1.f / rs1;

    const size_t row0 = (size_t)b*256 + p0 + m0 + g;
    #pragma unroll
    for (int dt = 0; dt < 4; dt++) {
        unsigned ub, us;
        int cu = (h*32 + dt*8 + 2*t) >> 1;
        split_pack(oacc[dt][0]*inv0, oacc[dt][1]*inv0, ub, us);
        g_attnb[row0*256 + cu] = ub; g_attns[row0*256 + cu] = us;
        split_pack(oacc[dt][2]*inv1, oacc[dt][3]*inv1, ub, us);
        g_attnb[(row0 + 8)*256 + cu] = ub; g_attns[(row0 + 8)*256 + cu] = us;
    }
}

// ---------------------------------------------------------------------------
// Pointer GEMM (pre-split) + tanh-clip softmax numerator. grid (8,2,32).
// ---------------------------------------------------------------------------
__global__ __launch_bounds__(256, 2) void pointer_k(const float* __restrict__ mask,
                                                    float* __restrict__ out)
{
    extern __shared__ unsigned smd[];
    const unsigned sbase = (unsigned)__cvta_generic_to_shared(smd);
    const int tid = threadIdx.x, lane = tid & 31, w = tid >> 5;
    const int g = lane >> 2, t = lane & 3;
    const int wm = w >> 2, wn = w & 3;
    const int b = blockIdx.z, pblk = blockIdx.y * 128, nblk = blockIdx.x * 128;
    const int mrow0 = b * 256 + pblk;
    const int nu0 = blockIdx.x * 64;

    float acc[4][4][4];
    #pragma unroll
    for (int i = 0; i < 4; i++) for (int j = 0; j < 4; j++) for (int r = 0; r < 4; r++)
        acc[i][j][r] = 0.f;

    auto stage = [&](int kt, int buf) {
        const int ku = kt * 16, k0 = kt * 32;
        #pragma unroll
        for (int i = 0; i < 8; i++) {
            int c = tid + i * 256;
            if (c < 1024) {
                int arr = c >> 9, j = c & 511;
                int row = j >> 2, c16 = j & 3;
                const unsigned* gp = arr ? g_mhs : g_mhb;
                cpa16(sbase + buf * 37888 + arr * 10240 + row * 80 + c16 * 16,
                      gp + (size_t)(mrow0 + row) * 256 + ku + c16 * 4);
            } else {
                int cb = c - 1024;
                int arr = cb >> 9, j = cb & 511;
                int row = j >> 4, c16 = j & 15;
                const unsigned* gp = arr ? g_shks : g_shkb;
                cpa16(sbase + buf * 37888 + 20480 + arr * 8704 + row * 272 + c16 * 16,
                      gp + ((size_t)(b * 512 + k0 + row)) * 512 + nu0 + c16 * 4);
            }
        }
        asm volatile("cp.async.commit_group;");
    };

    stage(0, 0);
    for (int kt = 0; kt < 16; kt++) {
        if (kt < 15) { stage(kt + 1, (kt + 1) & 1); asm volatile("cp.async.wait_group 1;"); }
        else         { asm volatile("cp.async.wait_group 0;"); }
        __syncthreads();
        const unsigned sb = sbase + (kt & 1) * 37888;
        #pragma unroll
        for (int ks = 0; ks < 2; ks++) {
            unsigned afb[4][4], afs[4][4];
            #pragma unroll
            for (int mt = 0; mt < 4; mt++) {
                unsigned ad = sb + (wm*64 + mt*16 + (lane & 15)) * 80 + (lane >> 4) * 16 + ks * 32;
                ldm4(afb[mt], ad);
                ldm4(afs[mt], ad + 10240);
            }
            #pragma unroll
            for (int ntp = 0; ntp < 2; ntp++) {
                unsigned bd = sb + 20480 + ((lane & 15) + ks * 16) * 272
                            + (wn*32 + ntp*16) * 2 + (lane >> 4) * 16;
                unsigned bb[4], bs2[4];
                ldm4t(bb, bd); ldm4t(bs2, bd + 8704);
                #pragma unroll
                for (int mt = 0; mt < 4; mt++) {
                    mma3(acc[mt][2*ntp],   afb[mt], afs[mt], bb,     bs2);
                    mma3(acc[mt][2*ntp+1], afb[mt], afs[mt], bb + 2, bs2 + 2);
                }
            }
        }
        __syncthreads();
    }

    const float invE = 0.04419417382415922f;
    #pragma unroll
    for (int mt = 0; mt < 4; mt++) {
        float rsl[2] = {0.f, 0.f};
        #pragma unroll
        for (int rr = 0; rr < 2; rr++) {
            const int p = pblk + wm*64 + mt*16 + g + rr*8;
            #pragma unroll
            for (int nt = 0; nt < 4; nt++) {
                const int n = nblk + wn*32 + nt*8 + 2*t;
                size_t oi = ((size_t)b*256 + p)*1024 + n;
                float2 mk = *(const float2*)(mask + oi);
                float e0 = __expf(10.f*tanhf(acc[mt][nt][rr*2]  *invE) + mk.x);
                float e1 = __expf(10.f*tanhf(acc[mt][nt][rr*2+1]*invE) + mk.y);
                rsl[rr] += e0 + e1;
                float2 o; o.x = e0; o.y = e1;
                *(float2*)(out + oi) = o;
            }
        }
        #pragma unroll
        for (int rr = 0; rr < 2; rr++) {
            float v = rsl[rr];
            v += __shfl_xor_sync(0xffffffffu, v, 1);
            v += __shfl_xor_sync(0xffffffffu, v, 2);
            if (t == 0)
                atomicAdd(&g_rowsum[b*256 + pblk + wm*64 + mt*16 + g + rr*8], v);
        }
    }
}

// ---------------------------------------------------------------------------
__global__ void zero_rowsum_k()
{
    int i = blockIdx.x * blockDim.x + threadIdx.x;
    if (i < Bn*Pn) g_rowsum[i] = 0.f;
}

__global__ void normalize_k(float* __restrict__ out)
{
    int i = blockIdx.x * blockDim.x + threadIdx.x;
    size_t i4 = (size_t)i * 4;
    int row = (int)(i4 >> 10);
    float inv = 1.f / g_rowsum[row];
    float4 v = *(float4*)&out[i4];
    v.x *= inv; v.y *= inv; v.z *= inv; v.w *= inv;
    *(float4*)&out[i4] = v;
}

// ---------------------------------------------------------------------------
extern "C" void kernel_launch(void* const* d_in, const int* in_sizes, int n_in,
                              void* d_out, int out_size)
{
    const float* enc  = (const float*)d_in[0];
    const float* mask = (const float*)d_in[1];
    const float* qf   = (const float*)d_in[2];
    const float* kmat = (const float*)d_in[3];
    const float* vmat = (const float*)d_in[4];
    const float* shk  = (const float*)d_in[5];
    const float* Wq   = (const float*)d_in[6];
    const float* Wc   = (const float*)d_in[7];
    float* out = (float*)d_out;

    unsigned *encb, *encs, *wqb, *wqs, *wcb, *wcs, *attnb, *attns, *mhb, *mhs, *shkb, *shks;
    unsigned *qb, *qs, *kb, *ks_, *vb, *vs;
    cudaGetSymbolAddress((void**)&encb, g_encb);  cudaGetSymbolAddress((void**)&encs, g_encs);
    cudaGetSymbolAddress((void**)&wqb,  g_Wqb);   cudaGetSymbolAddress((void**)&wqs,  g_Wqs);
    cudaGetSymbolAddress((void**)&wcb,  g_Wcb);   cudaGetSymbolAddress((void**)&wcs,  g_Wcs);
    cudaGetSymbolAddress((void**)&attnb,g_attnb); cudaGetSymbolAddress((void**)&attns,g_attns);
    cudaGetSymbolAddress((void**)&mhb,  g_mhb);   cudaGetSymbolAddress((void**)&mhs,  g_mhs);
    cudaGetSymbolAddress((void**)&shkb, g_shkb);  cudaGetSymbolAddress((void**)&shks, g_shks);
    cudaGetSymbolAddress((void**)&qb,   g_qb);    cudaGetSymbolAddress((void**)&qs,   g_qs);
    cudaGetSymbolAddress((void**)&kb,   g_kb);    cudaGetSymbolAddress((void**)&ks_,  g_ks);
    cudaGetSymbolAddress((void**)&vb,   g_vb);    cudaGetSymbolAddress((void**)&vs,   g_vs);

    cudaFuncSetAttribute(gemm_k<0>, cudaFuncAttributeMaxDynamicSharedMemorySize, 81920);
    cudaFuncSetAttribute(gemm_k<1>, cudaFuncAttributeMaxDynamicSharedMemorySize, 81920);
    cudaFuncSetAttribute(pointer_k, cudaFuncAttributeMaxDynamicSharedMemorySize, 75776);

    zero_rowsum_k<<<32, 256>>>();
    split_k<<<4096, 256>>>(enc, encb, encs, 1048576);
    split_k<<<256, 256>>>(Wq, wqb, wqs, 65536);
    split_k<<<256, 256>>>(Wc, wcb, wcs, 65536);
    split_k<<<16384, 256>>>(shk, shkb, shks, 4194304);
    split_k<<<16384, 256>>>(kmat, kb, ks_, 4194304);
    split_k<<<16384, 256>>>(vmat, vb, vs, 4194304);

    gemm_k<0><<<dim3(4, 64), 256, 81920>>>(encb, encs, wqb, wqs, qf, qb, qs);
    attn_k<<<dim3(512, 2), 256>>>(mask);
    gemm_k<1><<<dim3(4, 64), 256, 81920>>>(attnb, attns, wcb, wcs, nullptr, mhb, mhs);
    pointer_k<<<dim3(8, 2, 32), 256, 75776>>>(mask, out);
    normalize_k<<<8192, 256>>>(out);
}